// round 7
// baseline (speedup 1.0000x reference)
#include <cuda_runtime.h>
#include <cuda_fp16.h>
#include <math.h>
#include <stdint.h>

// Problem constants
#define BSZ 32
#define SSZ 512
#define DSZ 1024
#define LSZ 3
#define NTOK (BSZ * SSZ)   // 16384
#define NPAIR (NTOK / 2)   // 8192
#define INV_SQRT2f 0.70710678118654752440f
#define LN_EPSf 1e-5f

// ---------------------------------------------------------------------------
// Scratch (device globals)
// ---------------------------------------------------------------------------
__device__ float g_H[(size_t)NTOK * DSZ];        // hidden fp32 (final layer)
__device__ float g_C1[(size_t)NTOK * DSZ];
__device__ float g_C2[(size_t)NPAIR * DSZ];
__device__ __half g_Uh[(size_t)NTOK * DSZ];      // silu(h) hi/lo (fp16)
__device__ __half g_Ul[(size_t)NTOK * DSZ];
__device__ __half g_Hh[(size_t)NTOK * DSZ];      // h hi/lo (wav GEMM input)
__device__ __half g_Hl[(size_t)NTOK * DSZ];
__device__ __half g_bWh[(size_t)LSZ * DSZ * DSZ];
__device__ __half g_bWl[(size_t)LSZ * DSZ * DSZ];
__device__ __half g_wWh[(size_t)LSZ * DSZ * 2 * DSZ];  // combined [We|Wo]
__device__ __half g_wWl[(size_t)LSZ * DSZ * 2 * DSZ];

__device__ __forceinline__ float silu_f(float x) {
    return x / (1.0f + __expf(-x));
}

// hi/lo fp16 split: x = hi + lo + O(2^-22 x)
__device__ __forceinline__ void split_h(float x, __half& h, __half& l) {
    h = __float2half_rn(x);
    l = __float2half_rn(x - __half2float(h));
}

__device__ __forceinline__ uint32_t pack2h(__half a, __half b) {
    __half2 v = __halves2half2(a, b);
    return *reinterpret_cast<uint32_t*>(&v);
}

// ---------------------------------------------------------------------------
// PTX helpers
// ---------------------------------------------------------------------------
__device__ __forceinline__ uint32_t smem_u32(const void* p) {
    uint32_t a;
    asm("{ .reg .u64 t; cvta.to.shared.u64 t, %1; cvt.u32.u64 %0, t; }" : "=r"(a) : "l"(p));
    return a;
}
#define CP_ASYNC16(smem, gmem) \
    asm volatile("cp.async.cg.shared.global [%0], [%1], 16;" \
                 :: "r"((uint32_t)(smem)), "l"(gmem) : "memory")
#define CP_COMMIT() asm volatile("cp.async.commit_group;" ::: "memory")
#define CP_WAIT(n) asm volatile("cp.async.wait_group %0;" :: "n"(n) : "memory")

__device__ __forceinline__ void ldsm_x4(uint32_t& r0, uint32_t& r1, uint32_t& r2,
                                        uint32_t& r3, uint32_t addr) {
    asm volatile("ldmatrix.sync.aligned.m8n8.x4.shared.b16 {%0,%1,%2,%3}, [%4];"
                 : "=r"(r0), "=r"(r1), "=r"(r2), "=r"(r3) : "r"(addr));
}

// fp16 x fp16 -> fp32 accumulate (main pass)
__device__ __forceinline__ void mma16816f(float* c, const uint32_t* a, uint32_t b0,
                                          uint32_t b1) {
    asm volatile(
        "mma.sync.aligned.m16n8k16.row.col.f32.f16.f16.f32 "
        "{%0,%1,%2,%3}, {%4,%5,%6,%7}, {%8,%9}, {%0,%1,%2,%3};"
        : "+f"(c[0]), "+f"(c[1]), "+f"(c[2]), "+f"(c[3])
        : "r"(a[0]), "r"(a[1]), "r"(a[2]), "r"(a[3]), "r"(b0), "r"(b1));
}

// fp16 x fp16 -> fp16 accumulate (correction passes; 2 packed-half regs)
__device__ __forceinline__ void mma16816h(uint32_t* c, const uint32_t* a, uint32_t b0,
                                          uint32_t b1) {
    asm volatile(
        "mma.sync.aligned.m16n8k16.row.col.f16.f16.f16.f16 "
        "{%0,%1}, {%2,%3,%4,%5}, {%6,%7}, {%0,%1};"
        : "+r"(c[0]), "+r"(c[1])
        : "r"(a[0]), "r"(a[1]), "r"(a[2]), "r"(a[3]), "r"(b0), "r"(b1));
}

// ---------------------------------------------------------------------------
// Split-fp16 GEMM: C[M,1024] = (Ah+Al)[M,K] @ (Bh+Bl)[1024,K]^T, drop Al*Bl
// (~2^-24). Pass1 Ah*Bh in fp32-acc; corrections Ah*Bl + Al*Bh share one
// fp16 accumulator (2x rate hypothesis). CTA 128x128, 8 warps of 64x32,
// BK=32, 3-stage cp.async pipeline, 16B-chunk swizzle.
// ---------------------------------------------------------------------------
#define BK 32
#define ROWB 64
#define MAT_BYTES (128 * ROWB)        // 8 KB per operand tile
#define STAGE_BYTES (4 * MAT_BYTES)   // Ah, Al, Bh, Bl = 32 KB
#define NSTAGE 3
#define GEMM_SMEM (NSTAGE * STAGE_BYTES)  // 96 KB

__device__ __forceinline__ uint32_t swz(int row, int chunk) {
    return (uint32_t)(row * ROWB + ((chunk ^ ((row >> 1) & 3)) << 4));
}

__device__ __forceinline__ void load_stage(uint32_t st, const __half* Ah,
                                           const __half* Al, const __half* Bh,
                                           const __half* Bl, int K, int slab, int tid) {
    const __half* srcs[4] = {Ah, Al, Bh, Bl};
#pragma unroll
    for (int m = 0; m < 4; m++) {
        uint32_t mbase = st + m * MAT_BYTES;
        const __half* src = srcs[m];
#pragma unroll
        for (int j = 0; j < 2; j++) {
            int chunk = tid + j * 256;
            int row = chunk >> 2;
            int c = chunk & 3;
            const void* g = src + (size_t)row * K + slab * BK + c * 8;
            CP_ASYNC16(mbase + swz(row, c), g);
        }
    }
}

__global__ void __launch_bounds__(256) gemm_mma(const __half* __restrict__ Ah,
                                                const __half* __restrict__ Al,
                                                const __half* __restrict__ Bh,
                                                const __half* __restrict__ Bl,
                                                float* __restrict__ C, int K) {
    extern __shared__ char smem[];
    const uint32_t sb = smem_u32(smem);
    const int tid = threadIdx.x;
    const int wid = tid >> 5;
    const int lane = tid & 31;
    const int wm = wid >> 2;            // 0..1  -> m offset wm*64
    const int wn = wid & 3;             // 0..3  -> n offset wn*32
    const int bm = blockIdx.y, bn = blockIdx.x;

    const __half* Aht = Ah + (size_t)bm * 128 * K;
    const __half* Alt = Al + (size_t)bm * 128 * K;
    const __half* Bht = Bh + (size_t)bn * 128 * K;
    const __half* Blt = Bl + (size_t)bn * 128 * K;

    int arow[4], brow[2];
#pragma unroll
    for (int mt = 0; mt < 4; mt++) arow[mt] = wm * 64 + mt * 16 + (lane & 15);
#pragma unroll
    for (int np = 0; np < 2; np++) brow[np] = wn * 32 + np * 16 + (lane & 15);
    const int lchunk = lane >> 4;

    float acc[4][4][4];
    uint32_t acch[4][4][2];
#pragma unroll
    for (int i = 0; i < 4; i++)
#pragma unroll
        for (int j = 0; j < 4; j++) {
#pragma unroll
            for (int q = 0; q < 4; q++) acc[i][j][q] = 0.0f;
            acch[i][j][0] = 0u;
            acch[i][j][1] = 0u;
        }

    const int nslab = K / BK;
    load_stage(sb, Aht, Alt, Bht, Blt, K, 0, tid);
    CP_COMMIT();
    load_stage(sb + STAGE_BYTES, Aht, Alt, Bht, Blt, K, 1, tid);
    CP_COMMIT();

    for (int i = 0; i < nslab; i++) {
        CP_WAIT(1);
        __syncthreads();
        if (i + 2 < nslab) {
            load_stage(sb + ((i + 2) % NSTAGE) * STAGE_BYTES,
                       Aht, Alt, Bht, Blt, K, i + 2, tid);
            CP_COMMIT();
        }

        const uint32_t st = sb + (i % NSTAGE) * STAGE_BYTES;
        const uint32_t sAh = st, sAl = st + MAT_BYTES;
        const uint32_t sBh = st + 2 * MAT_BYTES, sBl = st + 3 * MAT_BYTES;

#pragma unroll
        for (int ks = 0; ks < BK / 16; ks++) {
            const int kc = lchunk + ks * 2;
            uint32_t ah[4][4], bh[2][4], bl[2][4];
#pragma unroll
            for (int mt = 0; mt < 4; mt++)
                ldsm_x4(ah[mt][0], ah[mt][1], ah[mt][2], ah[mt][3],
                        sAh + swz(arow[mt], kc));
#pragma unroll
            for (int np = 0; np < 2; np++)
                ldsm_x4(bh[np][0], bh[np][1], bh[np][2], bh[np][3],
                        sBh + swz(brow[np], kc));
#pragma unroll
            for (int np = 0; np < 2; np++)
                ldsm_x4(bl[np][0], bl[np][1], bl[np][2], bl[np][3],
                        sBl + swz(brow[np], kc));

            // Main pass: Ah*Bh -> fp32 acc
#pragma unroll
            for (int mt = 0; mt < 4; mt++)
#pragma unroll
                for (int nt = 0; nt < 4; nt++)
                    mma16816f(acc[mt][nt], ah[mt], bh[nt >> 1][nt & 1],
                              bh[nt >> 1][(nt & 1) + 2]);
            // Correction pass 1: Ah*Bl -> fp16 acc
#pragma unroll
            for (int mt = 0; mt < 4; mt++)
#pragma unroll
                for (int nt = 0; nt < 4; nt++)
                    mma16816h(acch[mt][nt], ah[mt], bl[nt >> 1][nt & 1],
                              bl[nt >> 1][(nt & 1) + 2]);
            // Correction pass 2: Al*Bh -> fp16 acc (reload al per mt)
            uint32_t al[4];
#pragma unroll
            for (int mt = 0; mt < 4; mt++) {
                ldsm_x4(al[0], al[1], al[2], al[3], sAl + swz(arow[mt], kc));
#pragma unroll
                for (int nt = 0; nt < 4; nt++)
                    mma16816h(acch[mt][nt], al, bh[nt >> 1][nt & 1],
                              bh[nt >> 1][(nt & 1) + 2]);
            }
        }
    }

    // Epilogue: C = acc32 + float(acc16)
    const int rbase = bm * 128 + wm * 64 + (lane >> 2);
    const int cbase = bn * 128 + wn * 32 + (lane & 3) * 2;
#pragma unroll
    for (int mt = 0; mt < 4; mt++)
#pragma unroll
        for (int nt = 0; nt < 4; nt++) {
            int r0 = rbase + mt * 16;
            int col = cbase + nt * 8;
            float2 c01 = __half22float2(*reinterpret_cast<__half2*>(&acch[mt][nt][0]));
            float2 c23 = __half22float2(*reinterpret_cast<__half2*>(&acch[mt][nt][1]));
            *reinterpret_cast<float2*>(C + (size_t)r0 * DSZ + col) =
                make_float2(acc[mt][nt][0] + c01.x, acc[mt][nt][1] + c01.y);
            *reinterpret_cast<float2*>(C + (size_t)(r0 + 8) * DSZ + col) =
                make_float2(acc[mt][nt][2] + c23.x, acc[mt][nt][3] + c23.y);
        }
}

// ---------------------------------------------------------------------------
// Elementwise / prep kernels
// ---------------------------------------------------------------------------
__global__ void __launch_bounds__(256) wsplit_kernel(const float* __restrict__ in,
                                                     __half* __restrict__ hi,
                                                     __half* __restrict__ lo) {
    size_t i = ((size_t)blockIdx.x * blockDim.x + threadIdx.x) * 4;
    float4 v = *reinterpret_cast<const float4*>(in + i);
    __half h0, h1, h2, h3, l0, l1, l2, l3;
    split_h(v.x, h0, l0); split_h(v.y, h1, l1);
    split_h(v.z, h2, l2); split_h(v.w, h3, l3);
    *reinterpret_cast<uint2*>(hi + i) = make_uint2(pack2h(h0, h1), pack2h(h2, h3));
    *reinterpret_cast<uint2*>(lo + i) = make_uint2(pack2h(l0, l1), pack2h(l2, l3));
}

// Combine wavelet weights: [Wa|Wd] -> [(Wa+Wd)/sqrt2 | (Wa-Wd)/sqrt2], fp16 split
__global__ void __launch_bounds__(256) wavprep_kernel(const float* __restrict__ wavW,
                                                      __half* __restrict__ hi,
                                                      __half* __restrict__ lo) {
    size_t idx = (size_t)blockIdx.x * blockDim.x + threadIdx.x;  // LSZ*DSZ*(DSZ/4)
    int k4 = (int)(idx % (DSZ / 4));
    size_t row = idx / (DSZ / 4);
    const float* base = wavW + row * (2 * DSZ);
    float4 wa = *reinterpret_cast<const float4*>(base + k4 * 4);
    float4 wd = *reinterpret_cast<const float4*>(base + DSZ + k4 * 4);
    float e0 = (wa.x + wd.x) * INV_SQRT2f, e1 = (wa.y + wd.y) * INV_SQRT2f;
    float e2 = (wa.z + wd.z) * INV_SQRT2f, e3 = (wa.w + wd.w) * INV_SQRT2f;
    float o0 = (wa.x - wd.x) * INV_SQRT2f, o1 = (wa.y - wd.y) * INV_SQRT2f;
    float o2 = (wa.z - wd.z) * INV_SQRT2f, o3 = (wa.w - wd.w) * INV_SQRT2f;
    size_t re = row * (2 * DSZ) + k4 * 4;
    size_t ro = re + DSZ;
    __half h0, h1, h2, h3, l0, l1, l2, l3;
    split_h(e0, h0, l0); split_h(e1, h1, l1); split_h(e2, h2, l2); split_h(e3, h3, l3);
    *reinterpret_cast<uint2*>(hi + re) = make_uint2(pack2h(h0, h1), pack2h(h2, h3));
    *reinterpret_cast<uint2*>(lo + re) = make_uint2(pack2h(l0, l1), pack2h(l2, l3));
    split_h(o0, h0, l0); split_h(o1, h1, l1); split_h(o2, h2, l2); split_h(o3, h3, l3);
    *reinterpret_cast<uint2*>(hi + ro) = make_uint2(pack2h(h0, h1), pack2h(h2, h3));
    *reinterpret_cast<uint2*>(lo + ro) = make_uint2(pack2h(l0, l1), pack2h(l2, l3));
}

// Layer-0 input prep: Hh/Hl = split(x), Uh/Ul = split(silu(x))
__global__ void __launch_bounds__(256) xprep_kernel(const float* __restrict__ in,
                                                    __half* __restrict__ Hh,
                                                    __half* __restrict__ Hl,
                                                    __half* __restrict__ Uh,
                                                    __half* __restrict__ Ul) {
    size_t i = ((size_t)blockIdx.x * blockDim.x + threadIdx.x) * 4;
    float4 v = *reinterpret_cast<const float4*>(in + i);
    __half h0, h1, h2, h3, l0, l1, l2, l3;
    split_h(v.x, h0, l0); split_h(v.y, h1, l1);
    split_h(v.z, h2, l2); split_h(v.w, h3, l3);
    *reinterpret_cast<uint2*>(Hh + i) = make_uint2(pack2h(h0, h1), pack2h(h2, h3));
    *reinterpret_cast<uint2*>(Hl + i) = make_uint2(pack2h(l0, l1), pack2h(l2, l3));
    float u0 = silu_f(v.x), u1 = silu_f(v.y), u2 = silu_f(v.z), u3 = silu_f(v.w);
    split_h(u0, h0, l0); split_h(u1, h1, l1);
    split_h(u2, h2, l2); split_h(u3, h3, l3);
    *reinterpret_cast<uint2*>(Uh + i) = make_uint2(pack2h(h0, h1), pack2h(h2, h3));
    *reinterpret_cast<uint2*>(Ul + i) = make_uint2(pack2h(l0, l1), pack2h(l2, l3));
}

__device__ __forceinline__ float block_sum_256(float v) {
    __shared__ float red[8];
    __shared__ float tot;
    int t = threadIdx.x;
#pragma unroll
    for (int o = 16; o > 0; o >>= 1) v += __shfl_xor_sync(0xffffffffu, v, o);
    __syncthreads();
    if ((t & 31) == 0) red[t >> 5] = v;
    __syncthreads();
    if (t == 0) {
        float s = 0.0f;
#pragma unroll
        for (int i = 0; i < 8; i++) s += red[i];
        tot = s;
    }
    __syncthreads();
    return tot;
}

// h = silu(LN(C1[r] + C2[r>>1])); non-final: fp16 splits of h and silu(h);
// final: fp32 H only.
__global__ void __launch_bounds__(256) lnact_kernel(const float* __restrict__ C1,
                                                    const float* __restrict__ C2,
                                                    const float* __restrict__ gamma,
                                                    const float* __restrict__ beta,
                                                    float* __restrict__ Hout,
                                                    __half* __restrict__ Hh,
                                                    __half* __restrict__ Hl,
                                                    __half* __restrict__ Uh,
                                                    __half* __restrict__ Ul,
                                                    int final_layer) {
    int r = blockIdx.x;
    int t = threadIdx.x;
    float4 v1 = *reinterpret_cast<const float4*>(C1 + (size_t)r * DSZ + t * 4);
    float4 v2 = *reinterpret_cast<const float4*>(C2 + (size_t)(r >> 1) * DSZ + t * 4);
    float x0 = v1.x + v2.x, x1 = v1.y + v2.y, x2 = v1.z + v2.z, x3 = v1.w + v2.w;

    float mu = block_sum_256(x0 + x1 + x2 + x3) * (1.0f / DSZ);
    float d0 = x0 - mu, d1 = x1 - mu, d2 = x2 - mu, d3 = x3 - mu;
    float var = block_sum_256(d0 * d0 + d1 * d1 + d2 * d2 + d3 * d3) * (1.0f / DSZ);
    float rs = rsqrtf(var + LN_EPSf);

    float4 g4 = *reinterpret_cast<const float4*>(gamma + t * 4);
    float4 b4 = *reinterpret_cast<const float4*>(beta + t * 4);
    float h0 = silu_f(d0 * rs * g4.x + b4.x);
    float h1 = silu_f(d1 * rs * g4.y + b4.y);
    float h2 = silu_f(d2 * rs * g4.z + b4.z);
    float h3 = silu_f(d3 * rs * g4.w + b4.w);

    size_t off = (size_t)r * DSZ + t * 4;
    if (final_layer) {
        *reinterpret_cast<float4*>(Hout + off) = make_float4(h0, h1, h2, h3);
        return;
    }

    __half a0, a1, a2, a3, c0, c1, c2, c3;
    split_h(h0, a0, c0); split_h(h1, a1, c1);
    split_h(h2, a2, c2); split_h(h3, a3, c3);
    *reinterpret_cast<uint2*>(Hh + off) = make_uint2(pack2h(a0, a1), pack2h(a2, a3));
    *reinterpret_cast<uint2*>(Hl + off) = make_uint2(pack2h(c0, c1), pack2h(c2, c3));

    float u0 = silu_f(h0), u1 = silu_f(h1), u2 = silu_f(h2), u3 = silu_f(h3);
    split_h(u0, a0, c0); split_h(u1, a1, c1);
    split_h(u2, a2, c2); split_h(u3, a3, c3);
    *reinterpret_cast<uint2*>(Uh + off) = make_uint2(pack2h(a0, a1), pack2h(a2, a3));
    *reinterpret_cast<uint2*>(Ul + off) = make_uint2(pack2h(c0, c1), pack2h(c2, c3));
}

__global__ void __launch_bounds__(1024) pool_kernel(const float* __restrict__ H,
                                                    const float* __restrict__ W,
                                                    const float* __restrict__ ob,
                                                    float* __restrict__ out) {
    __shared__ float red[32];
    int b = blockIdx.x, t = threadIdx.x;
    const float* Hb = H + (size_t)b * SSZ * DSZ + t;
    float cs = 0.0f;
#pragma unroll 8
    for (int s = 0; s < SSZ; s++) cs += Hb[(size_t)s * DSZ];
    float acc = cs * W[t];
#pragma unroll
    for (int o = 16; o > 0; o >>= 1) acc += __shfl_xor_sync(0xffffffffu, acc, o);
    if ((t & 31) == 0) red[t >> 5] = acc;
    __syncthreads();
    if (t < 32) {
        float v = red[t];
#pragma unroll
        for (int o = 16; o > 0; o >>= 1) v += __shfl_xor_sync(0xffffffffu, v, o);
        if (t == 0) out[b] = v * (1.0f / SSZ) + ob[0];
    }
}

// ---------------------------------------------------------------------------
// Launch
// ---------------------------------------------------------------------------
extern "C" void kernel_launch(void* const* d_in, const int* in_sizes, int n_in,
                              void* d_out, int out_size) {
    const float* x     = (const float*)d_in[0];
    const float* baseW = (const float*)d_in[1];
    const float* wavW  = (const float*)d_in[2];
    const float* lng   = (const float*)d_in[3];
    const float* lnb   = (const float*)d_in[4];
    const float* outW  = (const float*)d_in[5];
    const float* outb  = (const float*)d_in[6];
    float* out = (float*)d_out;

    float *H, *C1, *C2;
    __half *Uh, *Ul, *Hh, *Hl, *bWh, *bWl, *wWh, *wWl;
    cudaGetSymbolAddress((void**)&H, g_H);
    cudaGetSymbolAddress((void**)&C1, g_C1);
    cudaGetSymbolAddress((void**)&C2, g_C2);
    cudaGetSymbolAddress((void**)&Uh, g_Uh);
    cudaGetSymbolAddress((void**)&Ul, g_Ul);
    cudaGetSymbolAddress((void**)&Hh, g_Hh);
    cudaGetSymbolAddress((void**)&Hl, g_Hl);
    cudaGetSymbolAddress((void**)&bWh, g_bWh);
    cudaGetSymbolAddress((void**)&bWl, g_bWl);
    cudaGetSymbolAddress((void**)&wWh, g_wWh);
    cudaGetSymbolAddress((void**)&wWl, g_wWl);

    cudaFuncSetAttribute(gemm_mma, cudaFuncAttributeMaxDynamicSharedMemorySize,
                         GEMM_SMEM);

    // Prep (3 launches; 4th launch below = wav GEMM, ncu's profiled target)
    wsplit_kernel<<<(LSZ * DSZ * DSZ) / 1024, 256>>>(baseW, bWh, bWl);
    wavprep_kernel<<<(LSZ * DSZ * (DSZ / 4)) / 256, 256>>>(wavW, wWh, wWl);
    xprep_kernel<<<(NTOK * DSZ) / 1024, 256>>>(x, Hh, Hl, Uh, Ul);

    for (int l = 0; l < LSZ; l++) {
        // wav: H viewed as [8192, 2048] @ combined wW^T
        gemm_mma<<<dim3(DSZ / 128, NPAIR / 128), 256, GEMM_SMEM>>>(
            Hh, Hl, wWh + (size_t)l * DSZ * 2 * DSZ, wWl + (size_t)l * DSZ * 2 * DSZ,
            C2, 2 * DSZ);
        // base: U[16384,1024] @ bW^T
        gemm_mma<<<dim3(DSZ / 128, NTOK / 128), 256, GEMM_SMEM>>>(
            Uh, Ul, bWh + (size_t)l * DSZ * DSZ, bWl + (size_t)l * DSZ * DSZ, C1, DSZ);
        lnact_kernel<<<NTOK, 256>>>(C1, C2, lng + l * DSZ, lnb + l * DSZ,
                                    H, Hh, Hl, Uh, Ul, (l == LSZ - 1) ? 1 : 0);
    }
    pool_kernel<<<BSZ, 1024>>>(H, outW, outb, out);
}

// round 8
// speedup vs baseline: 1.1202x; 1.1202x over previous
#include <cuda_runtime.h>
#include <cuda_fp16.h>
#include <math.h>
#include <stdint.h>

// Problem constants
#define BSZ 32
#define SSZ 512
#define DSZ 1024
#define LSZ 3
#define NTOK (BSZ * SSZ)   // 16384
#define NPAIR (NTOK / 2)   // 8192
#define INV_SQRT2f 0.70710678118654752440f
#define LN_EPSf 1e-5f

// ---------------------------------------------------------------------------
// Scratch (device globals)
// ---------------------------------------------------------------------------
__device__ float g_H[(size_t)NTOK * DSZ];        // hidden fp32 (final layer)
__device__ float g_C1[(size_t)NTOK * DSZ];
__device__ float g_C2[(size_t)NPAIR * DSZ];
__device__ __half g_Uh[(size_t)NTOK * DSZ];      // silu(h) hi/lo (fp16)
__device__ __half g_Ul[(size_t)NTOK * DSZ];
__device__ __half g_Hh[(size_t)NTOK * DSZ];      // h hi/lo (wav GEMM input)
__device__ __half g_Hl[(size_t)NTOK * DSZ];
__device__ __half g_bWh[(size_t)LSZ * DSZ * DSZ];
__device__ __half g_bWl[(size_t)LSZ * DSZ * DSZ];
__device__ __half g_wWh[(size_t)LSZ * DSZ * 2 * DSZ];  // combined [We|Wo]
__device__ __half g_wWl[(size_t)LSZ * DSZ * 2 * DSZ];

__device__ __forceinline__ float silu_f(float x) {
    return x / (1.0f + __expf(-x));
}

// hi/lo fp16 split: x = hi + lo + O(2^-22 x)
__device__ __forceinline__ void split_h(float x, __half& h, __half& l) {
    h = __float2half_rn(x);
    l = __float2half_rn(x - __half2float(h));
}

__device__ __forceinline__ uint32_t pack2h(__half a, __half b) {
    __half2 v = __halves2half2(a, b);
    return *reinterpret_cast<uint32_t*>(&v);
}

// ---------------------------------------------------------------------------
// PTX helpers
// ---------------------------------------------------------------------------
__device__ __forceinline__ uint32_t smem_u32(const void* p) {
    uint32_t a;
    asm("{ .reg .u64 t; cvta.to.shared.u64 t, %1; cvt.u32.u64 %0, t; }" : "=r"(a) : "l"(p));
    return a;
}
#define CP_ASYNC16(smem, gmem) \
    asm volatile("cp.async.cg.shared.global [%0], [%1], 16;" \
                 :: "r"((uint32_t)(smem)), "l"(gmem) : "memory")
#define CP_COMMIT() asm volatile("cp.async.commit_group;" ::: "memory")
#define CP_WAIT(n) asm volatile("cp.async.wait_group %0;" :: "n"(n) : "memory")

__device__ __forceinline__ void ldsm_x4(uint32_t& r0, uint32_t& r1, uint32_t& r2,
                                        uint32_t& r3, uint32_t addr) {
    asm volatile("ldmatrix.sync.aligned.m8n8.x4.shared.b16 {%0,%1,%2,%3}, [%4];"
                 : "=r"(r0), "=r"(r1), "=r"(r2), "=r"(r3) : "r"(addr));
}

// fp16 x fp16 -> fp32 accumulate
__device__ __forceinline__ void mma16816f(float* c, const uint32_t* a, uint32_t b0,
                                          uint32_t b1) {
    asm volatile(
        "mma.sync.aligned.m16n8k16.row.col.f32.f16.f16.f32 "
        "{%0,%1,%2,%3}, {%4,%5,%6,%7}, {%8,%9}, {%0,%1,%2,%3};"
        : "+f"(c[0]), "+f"(c[1]), "+f"(c[2]), "+f"(c[3])
        : "r"(a[0]), "r"(a[1]), "r"(a[2]), "r"(a[3]), "r"(b0), "r"(b1));
}

// ---------------------------------------------------------------------------
// Split-fp16 GEMM: C[M,1024] = (Ah+Al)[M,K] @ (Bh+Bl)[1024,K]^T, drop Al*Bl
// (~2^-24). CTA 128x128, 8 warps of 64x32, BK=32, 2-stage cp.async pipeline
// (64KB smem -> 2 CTAs/SM = 16 warps/SM for latency hiding).
// ---------------------------------------------------------------------------
#define BK 32
#define ROWB 64
#define MAT_BYTES (128 * ROWB)        // 8 KB per operand tile
#define STAGE_BYTES (4 * MAT_BYTES)   // Ah, Al, Bh, Bl = 32 KB
#define NSTAGE 2
#define GEMM_SMEM (NSTAGE * STAGE_BYTES)  // 64 KB

__device__ __forceinline__ uint32_t swz(int row, int chunk) {
    return (uint32_t)(row * ROWB + ((chunk ^ ((row >> 1) & 3)) << 4));
}

__device__ __forceinline__ void load_stage(uint32_t st, const __half* Ah,
                                           const __half* Al, const __half* Bh,
                                           const __half* Bl, int K, int slab, int tid) {
    const __half* srcs[4] = {Ah, Al, Bh, Bl};
#pragma unroll
    for (int m = 0; m < 4; m++) {
        uint32_t mbase = st + m * MAT_BYTES;
        const __half* src = srcs[m];
#pragma unroll
        for (int j = 0; j < 2; j++) {
            int chunk = tid + j * 256;
            int row = chunk >> 2;
            int c = chunk & 3;
            const void* g = src + (size_t)row * K + slab * BK + c * 8;
            CP_ASYNC16(mbase + swz(row, c), g);
        }
    }
}

__global__ void __launch_bounds__(256, 2) gemm_mma(const __half* __restrict__ Ah,
                                                   const __half* __restrict__ Al,
                                                   const __half* __restrict__ Bh,
                                                   const __half* __restrict__ Bl,
                                                   float* __restrict__ C, int K) {
    extern __shared__ char smem[];
    const uint32_t sb = smem_u32(smem);
    const int tid = threadIdx.x;
    const int wid = tid >> 5;
    const int lane = tid & 31;
    const int wm = wid >> 2;            // 0..1  -> m offset wm*64
    const int wn = wid & 3;             // 0..3  -> n offset wn*32
    const int bm = blockIdx.y, bn = blockIdx.x;

    const __half* Aht = Ah + (size_t)bm * 128 * K;
    const __half* Alt = Al + (size_t)bm * 128 * K;
    const __half* Bht = Bh + (size_t)bn * 128 * K;
    const __half* Blt = Bl + (size_t)bn * 128 * K;

    int arow[4], brow[2];
#pragma unroll
    for (int mt = 0; mt < 4; mt++) arow[mt] = wm * 64 + mt * 16 + (lane & 15);
#pragma unroll
    for (int np = 0; np < 2; np++) brow[np] = wn * 32 + np * 16 + (lane & 15);
    const int lchunk = lane >> 4;

    float acc[4][4][4];
#pragma unroll
    for (int i = 0; i < 4; i++)
#pragma unroll
        for (int j = 0; j < 4; j++)
#pragma unroll
            for (int q = 0; q < 4; q++) acc[i][j][q] = 0.0f;

    const int nslab = K / BK;
    load_stage(sb, Aht, Alt, Bht, Blt, K, 0, tid);
    CP_COMMIT();
    load_stage(sb + STAGE_BYTES, Aht, Alt, Bht, Blt, K, 1, tid);
    CP_COMMIT();

    for (int i = 0; i < nslab; i++) {
        CP_WAIT(1);                     // stage i's group complete
        __syncthreads();

        const uint32_t st = sb + (i & 1) * STAGE_BYTES;
        const uint32_t sAh = st, sAl = st + MAT_BYTES;
        const uint32_t sBh = st + 2 * MAT_BYTES, sBl = st + 3 * MAT_BYTES;

#pragma unroll
        for (int ks = 0; ks < BK / 16; ks++) {
            const int kc = lchunk + ks * 2;
            uint32_t ah[4][4], bh[2][4], bl[2][4];
#pragma unroll
            for (int mt = 0; mt < 4; mt++)
                ldsm_x4(ah[mt][0], ah[mt][1], ah[mt][2], ah[mt][3],
                        sAh + swz(arow[mt], kc));
#pragma unroll
            for (int np = 0; np < 2; np++)
                ldsm_x4(bh[np][0], bh[np][1], bh[np][2], bh[np][3],
                        sBh + swz(brow[np], kc));
#pragma unroll
            for (int np = 0; np < 2; np++)
                ldsm_x4(bl[np][0], bl[np][1], bl[np][2], bl[np][3],
                        sBl + swz(brow[np], kc));

            // Ah*Bh + Ah*Bl (fp32 acc)
#pragma unroll
            for (int mt = 0; mt < 4; mt++)
#pragma unroll
                for (int nt = 0; nt < 4; nt++) {
                    mma16816f(acc[mt][nt], ah[mt], bh[nt >> 1][nt & 1],
                              bh[nt >> 1][(nt & 1) + 2]);
                    mma16816f(acc[mt][nt], ah[mt], bl[nt >> 1][nt & 1],
                              bl[nt >> 1][(nt & 1) + 2]);
                }
            // Al*Bh (reload al per mt to cap registers)
            uint32_t al[4];
#pragma unroll
            for (int mt = 0; mt < 4; mt++) {
                ldsm_x4(al[0], al[1], al[2], al[3], sAl + swz(arow[mt], kc));
#pragma unroll
                for (int nt = 0; nt < 4; nt++)
                    mma16816f(acc[mt][nt], al, bh[nt >> 1][nt & 1],
                              bh[nt >> 1][(nt & 1) + 2]);
            }
        }

        __syncthreads();                // all warps done reading before refill
        if (i + 2 < nslab) {
            load_stage(st, Aht, Alt, Bht, Blt, K, i + 2, tid);
            CP_COMMIT();
        }
    }

    const int rbase = bm * 128 + wm * 64 + (lane >> 2);
    const int cbase = bn * 128 + wn * 32 + (lane & 3) * 2;
#pragma unroll
    for (int mt = 0; mt < 4; mt++)
#pragma unroll
        for (int nt = 0; nt < 4; nt++) {
            int r0 = rbase + mt * 16;
            int col = cbase + nt * 8;
            *reinterpret_cast<float2*>(C + (size_t)r0 * DSZ + col) =
                make_float2(acc[mt][nt][0], acc[mt][nt][1]);
            *reinterpret_cast<float2*>(C + (size_t)(r0 + 8) * DSZ + col) =
                make_float2(acc[mt][nt][2], acc[mt][nt][3]);
        }
}

// ---------------------------------------------------------------------------
// Elementwise / prep kernels
// ---------------------------------------------------------------------------
__global__ void __launch_bounds__(256) wsplit_kernel(const float* __restrict__ in,
                                                     __half* __restrict__ hi,
                                                     __half* __restrict__ lo) {
    size_t i = ((size_t)blockIdx.x * blockDim.x + threadIdx.x) * 4;
    float4 v = *reinterpret_cast<const float4*>(in + i);
    __half h0, h1, h2, h3, l0, l1, l2, l3;
    split_h(v.x, h0, l0); split_h(v.y, h1, l1);
    split_h(v.z, h2, l2); split_h(v.w, h3, l3);
    *reinterpret_cast<uint2*>(hi + i) = make_uint2(pack2h(h0, h1), pack2h(h2, h3));
    *reinterpret_cast<uint2*>(lo + i) = make_uint2(pack2h(l0, l1), pack2h(l2, l3));
}

// Combine wavelet weights: [Wa|Wd] -> [(Wa+Wd)/sqrt2 | (Wa-Wd)/sqrt2], fp16 split
__global__ void __launch_bounds__(256) wavprep_kernel(const float* __restrict__ wavW,
                                                      __half* __restrict__ hi,
                                                      __half* __restrict__ lo) {
    size_t idx = (size_t)blockIdx.x * blockDim.x + threadIdx.x;  // LSZ*DSZ*(DSZ/4)
    int k4 = (int)(idx % (DSZ / 4));
    size_t row = idx / (DSZ / 4);
    const float* base = wavW + row * (2 * DSZ);
    float4 wa = *reinterpret_cast<const float4*>(base + k4 * 4);
    float4 wd = *reinterpret_cast<const float4*>(base + DSZ + k4 * 4);
    float e0 = (wa.x + wd.x) * INV_SQRT2f, e1 = (wa.y + wd.y) * INV_SQRT2f;
    float e2 = (wa.z + wd.z) * INV_SQRT2f, e3 = (wa.w + wd.w) * INV_SQRT2f;
    float o0 = (wa.x - wd.x) * INV_SQRT2f, o1 = (wa.y - wd.y) * INV_SQRT2f;
    float o2 = (wa.z - wd.z) * INV_SQRT2f, o3 = (wa.w - wd.w) * INV_SQRT2f;
    size_t re = row * (2 * DSZ) + k4 * 4;
    size_t ro = re + DSZ;
    __half h0, h1, h2, h3, l0, l1, l2, l3;
    split_h(e0, h0, l0); split_h(e1, h1, l1); split_h(e2, h2, l2); split_h(e3, h3, l3);
    *reinterpret_cast<uint2*>(hi + re) = make_uint2(pack2h(h0, h1), pack2h(h2, h3));
    *reinterpret_cast<uint2*>(lo + re) = make_uint2(pack2h(l0, l1), pack2h(l2, l3));
    split_h(o0, h0, l0); split_h(o1, h1, l1); split_h(o2, h2, l2); split_h(o3, h3, l3);
    *reinterpret_cast<uint2*>(hi + ro) = make_uint2(pack2h(h0, h1), pack2h(h2, h3));
    *reinterpret_cast<uint2*>(lo + ro) = make_uint2(pack2h(l0, l1), pack2h(l2, l3));
}

// Layer-0 input prep: Hh/Hl = split(x), Uh/Ul = split(silu(x))
__global__ void __launch_bounds__(256) xprep_kernel(const float* __restrict__ in,
                                                    __half* __restrict__ Hh,
                                                    __half* __restrict__ Hl,
                                                    __half* __restrict__ Uh,
                                                    __half* __restrict__ Ul) {
    size_t i = ((size_t)blockIdx.x * blockDim.x + threadIdx.x) * 4;
    float4 v = *reinterpret_cast<const float4*>(in + i);
    __half h0, h1, h2, h3, l0, l1, l2, l3;
    split_h(v.x, h0, l0); split_h(v.y, h1, l1);
    split_h(v.z, h2, l2); split_h(v.w, h3, l3);
    *reinterpret_cast<uint2*>(Hh + i) = make_uint2(pack2h(h0, h1), pack2h(h2, h3));
    *reinterpret_cast<uint2*>(Hl + i) = make_uint2(pack2h(l0, l1), pack2h(l2, l3));
    float u0 = silu_f(v.x), u1 = silu_f(v.y), u2 = silu_f(v.z), u3 = silu_f(v.w);
    split_h(u0, h0, l0); split_h(u1, h1, l1);
    split_h(u2, h2, l2); split_h(u3, h3, l3);
    *reinterpret_cast<uint2*>(Uh + i) = make_uint2(pack2h(h0, h1), pack2h(h2, h3));
    *reinterpret_cast<uint2*>(Ul + i) = make_uint2(pack2h(l0, l1), pack2h(l2, l3));
}

__device__ __forceinline__ float block_sum_256(float v) {
    __shared__ float red[8];
    __shared__ float tot;
    int t = threadIdx.x;
#pragma unroll
    for (int o = 16; o > 0; o >>= 1) v += __shfl_xor_sync(0xffffffffu, v, o);
    __syncthreads();
    if ((t & 31) == 0) red[t >> 5] = v;
    __syncthreads();
    if (t == 0) {
        float s = 0.0f;
#pragma unroll
        for (int i = 0; i < 8; i++) s += red[i];
        tot = s;
    }
    __syncthreads();
    return tot;
}

// h = silu(LN(C1[r] + C2[r>>1])); non-final: fp16 splits of h and silu(h);
// final: fp32 H only.
__global__ void __launch_bounds__(256) lnact_kernel(const float* __restrict__ C1,
                                                    const float* __restrict__ C2,
                                                    const float* __restrict__ gamma,
                                                    const float* __restrict__ beta,
                                                    float* __restrict__ Hout,
                                                    __half* __restrict__ Hh,
                                                    __half* __restrict__ Hl,
                                                    __half* __restrict__ Uh,
                                                    __half* __restrict__ Ul,
                                                    int final_layer) {
    int r = blockIdx.x;
    int t = threadIdx.x;
    float4 v1 = *reinterpret_cast<const float4*>(C1 + (size_t)r * DSZ + t * 4);
    float4 v2 = *reinterpret_cast<const float4*>(C2 + (size_t)(r >> 1) * DSZ + t * 4);
    float x0 = v1.x + v2.x, x1 = v1.y + v2.y, x2 = v1.z + v2.z, x3 = v1.w + v2.w;

    float mu = block_sum_256(x0 + x1 + x2 + x3) * (1.0f / DSZ);
    float d0 = x0 - mu, d1 = x1 - mu, d2 = x2 - mu, d3 = x3 - mu;
    float var = block_sum_256(d0 * d0 + d1 * d1 + d2 * d2 + d3 * d3) * (1.0f / DSZ);
    float rs = rsqrtf(var + LN_EPSf);

    float4 g4 = *reinterpret_cast<const float4*>(gamma + t * 4);
    float4 b4 = *reinterpret_cast<const float4*>(beta + t * 4);
    float h0 = silu_f(d0 * rs * g4.x + b4.x);
    float h1 = silu_f(d1 * rs * g4.y + b4.y);
    float h2 = silu_f(d2 * rs * g4.z + b4.z);
    float h3 = silu_f(d3 * rs * g4.w + b4.w);

    size_t off = (size_t)r * DSZ + t * 4;
    if (final_layer) {
        *reinterpret_cast<float4*>(Hout + off) = make_float4(h0, h1, h2, h3);
        return;
    }

    __half a0, a1, a2, a3, c0, c1, c2, c3;
    split_h(h0, a0, c0); split_h(h1, a1, c1);
    split_h(h2, a2, c2); split_h(h3, a3, c3);
    *reinterpret_cast<uint2*>(Hh + off) = make_uint2(pack2h(a0, a1), pack2h(a2, a3));
    *reinterpret_cast<uint2*>(Hl + off) = make_uint2(pack2h(c0, c1), pack2h(c2, c3));

    float u0 = silu_f(h0), u1 = silu_f(h1), u2 = silu_f(h2), u3 = silu_f(h3);
    split_h(u0, a0, c0); split_h(u1, a1, c1);
    split_h(u2, a2, c2); split_h(u3, a3, c3);
    *reinterpret_cast<uint2*>(Uh + off) = make_uint2(pack2h(a0, a1), pack2h(a2, a3));
    *reinterpret_cast<uint2*>(Ul + off) = make_uint2(pack2h(c0, c1), pack2h(c2, c3));
}

__global__ void __launch_bounds__(1024) pool_kernel(const float* __restrict__ H,
                                                    const float* __restrict__ W,
                                                    const float* __restrict__ ob,
                                                    float* __restrict__ out) {
    __shared__ float red[32];
    int b = blockIdx.x, t = threadIdx.x;
    const float* Hb = H + (size_t)b * SSZ * DSZ + t;
    float cs = 0.0f;
#pragma unroll 8
    for (int s = 0; s < SSZ; s++) cs += Hb[(size_t)s * DSZ];
    float acc = cs * W[t];
#pragma unroll
    for (int o = 16; o > 0; o >>= 1) acc += __shfl_xor_sync(0xffffffffu, acc, o);
    if ((t & 31) == 0) red[t >> 5] = acc;
    __syncthreads();
    if (t < 32) {
        float v = red[t];
#pragma unroll
        for (int o = 16; o > 0; o >>= 1) v += __shfl_xor_sync(0xffffffffu, v, o);
        if (t == 0) out[b] = v * (1.0f / SSZ) + ob[0];
    }
}

// ---------------------------------------------------------------------------
// Launch
// ---------------------------------------------------------------------------
extern "C" void kernel_launch(void* const* d_in, const int* in_sizes, int n_in,
                              void* d_out, int out_size) {
    const float* x     = (const float*)d_in[0];
    const float* baseW = (const float*)d_in[1];
    const float* wavW  = (const float*)d_in[2];
    const float* lng   = (const float*)d_in[3];
    const float* lnb   = (const float*)d_in[4];
    const float* outW  = (const float*)d_in[5];
    const float* outb  = (const float*)d_in[6];
    float* out = (float*)d_out;

    float *H, *C1, *C2;
    __half *Uh, *Ul, *Hh, *Hl, *bWh, *bWl, *wWh, *wWl;
    cudaGetSymbolAddress((void**)&H, g_H);
    cudaGetSymbolAddress((void**)&C1, g_C1);
    cudaGetSymbolAddress((void**)&C2, g_C2);
    cudaGetSymbolAddress((void**)&Uh, g_Uh);
    cudaGetSymbolAddress((void**)&Ul, g_Ul);
    cudaGetSymbolAddress((void**)&Hh, g_Hh);
    cudaGetSymbolAddress((void**)&Hl, g_Hl);
    cudaGetSymbolAddress((void**)&bWh, g_bWh);
    cudaGetSymbolAddress((void**)&bWl, g_bWl);
    cudaGetSymbolAddress((void**)&wWh, g_wWh);
    cudaGetSymbolAddress((void**)&wWl, g_wWl);

    cudaFuncSetAttribute(gemm_mma, cudaFuncAttributeMaxDynamicSharedMemorySize,
                         GEMM_SMEM);

    // Prep (3 launches; 4th launch below = wav GEMM, ncu's profiled target)
    wsplit_kernel<<<(LSZ * DSZ * DSZ) / 1024, 256>>>(baseW, bWh, bWl);
    wavprep_kernel<<<(LSZ * DSZ * (DSZ / 4)) / 256, 256>>>(wavW, wWh, wWl);
    xprep_kernel<<<(NTOK * DSZ) / 1024, 256>>>(x, Hh, Hl, Uh, Ul);

    for (int l = 0; l < LSZ; l++) {
        // wav: H viewed as [8192, 2048] @ combined wW^T
        gemm_mma<<<dim3(DSZ / 128, NPAIR / 128), 256, GEMM_SMEM>>>(
            Hh, Hl, wWh + (size_t)l * DSZ * 2 * DSZ, wWl + (size_t)l * DSZ * 2 * DSZ,
            C2, 2 * DSZ);
        // base: U[16384,1024] @ bW^T
        gemm_mma<<<dim3(DSZ / 128, NTOK / 128), 256, GEMM_SMEM>>>(
            Uh, Ul, bWh + (size_t)l * DSZ * DSZ, bWl + (size_t)l * DSZ * DSZ, C1, DSZ);
        lnact_kernel<<<NTOK, 256>>>(C1, C2, lng + l * DSZ, lnb + l * DSZ,
                                    H, Hh, Hl, Uh, Ul, (l == LSZ - 1) ? 1 : 0);
    }
    pool_kernel<<<BSZ, 1024>>>(H, outW, outb, out);
}

// round 11
// speedup vs baseline: 1.5895x; 1.4189x over previous
#include <cuda_runtime.h>
#include <cuda_fp16.h>
#include <math.h>
#include <stdint.h>

// Problem constants
#define BSZ 32
#define SSZ 512
#define DSZ 1024
#define LSZ 3
#define NTOK (BSZ * SSZ)   // 16384
#define NPAIR (NTOK / 2)   // 8192
#define INV_SQRT2f 0.70710678118654752440f
#define LN_EPSf 1e-5f

// ---------------------------------------------------------------------------
// Scratch (device globals)
// ---------------------------------------------------------------------------
__device__ float g_H[(size_t)NTOK * DSZ];        // hidden fp32 (final layer)
__device__ float g_C1[(size_t)NTOK * DSZ];
__device__ float g_C2[(size_t)NPAIR * DSZ];
__device__ __half g_U[(size_t)NTOK * DSZ];       // silu(h), fp16 (base GEMM A)
__device__ __half g_Hx[(size_t)NTOK * DSZ];      // h, fp16 (wav GEMM A)
__device__ __half g_bWh[(size_t)LSZ * DSZ * DSZ];       // base weights hi/lo
__device__ __half g_bWl[(size_t)LSZ * DSZ * DSZ];
__device__ __half g_wWh[(size_t)LSZ * DSZ * 2 * DSZ];   // combined [We|Wo] hi/lo
__device__ __half g_wWl[(size_t)LSZ * DSZ * 2 * DSZ];

__device__ __forceinline__ float silu_f(float x) {
    return x / (1.0f + __expf(-x));
}

// hi/lo fp16 split: x = hi + lo + O(2^-22 x)
__device__ __forceinline__ void split_h(float x, __half& h, __half& l) {
    h = __float2half_rn(x);
    l = __float2half_rn(x - __half2float(h));
}

__device__ __forceinline__ uint32_t pack2h(__half a, __half b) {
    __half2 v = __halves2half2(a, b);
    return *reinterpret_cast<uint32_t*>(&v);
}

// ---------------------------------------------------------------------------
// PTX helpers
// ---------------------------------------------------------------------------
__device__ __forceinline__ uint32_t smem_u32(const void* p) {
    uint32_t a;
    asm("{ .reg .u64 t; cvta.to.shared.u64 t, %1; cvt.u32.u64 %0, t; }" : "=r"(a) : "l"(p));
    return a;
}
#define CP_ASYNC16(smem, gmem) \
    asm volatile("cp.async.cg.shared.global [%0], [%1], 16;" \
                 :: "r"((uint32_t)(smem)), "l"(gmem) : "memory")
#define CP_COMMIT() asm volatile("cp.async.commit_group;" ::: "memory")
#define CP_WAIT(n) asm volatile("cp.async.wait_group %0;" :: "n"(n) : "memory")

__device__ __forceinline__ void ldsm_x4(uint32_t& r0, uint32_t& r1, uint32_t& r2,
                                        uint32_t& r3, uint32_t addr) {
    asm volatile("ldmatrix.sync.aligned.m8n8.x4.shared.b16 {%0,%1,%2,%3}, [%4];"
                 : "=r"(r0), "=r"(r1), "=r"(r2), "=r"(r3) : "r"(addr));
}

// fp16 x fp16 -> fp32 accumulate
__device__ __forceinline__ void mma16816f(float* c, const uint32_t* a, uint32_t b0,
                                          uint32_t b1) {
    asm volatile(
        "mma.sync.aligned.m16n8k16.row.col.f32.f16.f16.f32 "
        "{%0,%1,%2,%3}, {%4,%5,%6,%7}, {%8,%9}, {%0,%1,%2,%3};"
        : "+f"(c[0]), "+f"(c[1]), "+f"(c[2]), "+f"(c[3])
        : "r"(a[0]), "r"(a[1]), "r"(a[2]), "r"(a[3]), "r"(b0), "r"(b1));
}

// ---------------------------------------------------------------------------
// GEMM: C[M,1024] = A[M,K] @ (Bh+Bl)[1024,K]^T.  A single fp16 (activations,
// error 2^-12 rel); weights exact as hi+lo fp16. 2 MMA passes per k-step.
// CTA 128x128, 8 warps of 64x32, BK=32, 3-stage cp.async, 2 CTAs/SM.
// ---------------------------------------------------------------------------
#define BK 32
#define ROWB 64
#define MAT_BYTES (128 * ROWB)        // 8 KB per operand tile
#define STAGE_BYTES (3 * MAT_BYTES)   // A, Bh, Bl = 24 KB
#define NSTAGE 3
#define GEMM_SMEM (NSTAGE * STAGE_BYTES)  // 72 KB

__device__ __forceinline__ uint32_t swz(int row, int chunk) {
    return (uint32_t)(row * ROWB + ((chunk ^ ((row >> 1) & 3)) << 4));
}

__device__ __forceinline__ void load_stage(uint32_t st, const __half* A,
                                           const __half* Bh, const __half* Bl,
                                           int K, int slab, int tid) {
    const __half* srcs[3] = {A, Bh, Bl};
#pragma unroll
    for (int m = 0; m < 3; m++) {
        uint32_t mbase = st + m * MAT_BYTES;
        const __half* src = srcs[m];
#pragma unroll
        for (int j = 0; j < 2; j++) {
            int chunk = tid + j * 256;
            int row = chunk >> 2;
            int c = chunk & 3;
            const void* g = src + (size_t)row * K + slab * BK + c * 8;
            CP_ASYNC16(mbase + swz(row, c), g);
        }
    }
}

__global__ void __launch_bounds__(256, 2) gemm_mma(const __half* __restrict__ A,
                                                   const __half* __restrict__ Bh,
                                                   const __half* __restrict__ Bl,
                                                   float* __restrict__ C, int K) {
    extern __shared__ char smem[];
    const uint32_t sb = smem_u32(smem);
    const int tid = threadIdx.x;
    const int wid = tid >> 5;
    const int lane = tid & 31;
    const int wm = wid >> 2;            // 0..1  -> m offset wm*64
    const int wn = wid & 3;             // 0..3  -> n offset wn*32
    const int bm = blockIdx.y, bn = blockIdx.x;

    const __half* At = A + (size_t)bm * 128 * K;
    const __half* Bht = Bh + (size_t)bn * 128 * K;
    const __half* Blt = Bl + (size_t)bn * 128 * K;

    int arow[4], brow[2];
#pragma unroll
    for (int mt = 0; mt < 4; mt++) arow[mt] = wm * 64 + mt * 16 + (lane & 15);
#pragma unroll
    for (int np = 0; np < 2; np++) brow[np] = wn * 32 + np * 16 + (lane & 15);
    const int lchunk = lane >> 4;

    float acc[4][4][4];
#pragma unroll
    for (int i = 0; i < 4; i++)
#pragma unroll
        for (int j = 0; j < 4; j++)
#pragma unroll
            for (int q = 0; q < 4; q++) acc[i][j][q] = 0.0f;

    const int nslab = K / BK;
    load_stage(sb, At, Bht, Blt, K, 0, tid);
    CP_COMMIT();
    load_stage(sb + STAGE_BYTES, At, Bht, Blt, K, 1, tid);
    CP_COMMIT();

    for (int i = 0; i < nslab; i++) {
        CP_WAIT(1);
        __syncthreads();                // all warps finished stage i-1 compute
        if (i + 2 < nslab) {
            load_stage(sb + ((i + 2) % NSTAGE) * STAGE_BYTES,
                       At, Bht, Blt, K, i + 2, tid);
            CP_COMMIT();
        }

        const uint32_t st = sb + (i % NSTAGE) * STAGE_BYTES;
        const uint32_t sA = st;
        const uint32_t sBh = st + MAT_BYTES, sBl = st + 2 * MAT_BYTES;

#pragma unroll
        for (int ks = 0; ks < BK / 16; ks++) {
            const int kc = lchunk + ks * 2;
            uint32_t ah[4][4], bh[2][4], bl[2][4];
#pragma unroll
            for (int mt = 0; mt < 4; mt++)
                ldsm_x4(ah[mt][0], ah[mt][1], ah[mt][2], ah[mt][3],
                        sA + swz(arow[mt], kc));
#pragma unroll
            for (int np = 0; np < 2; np++)
                ldsm_x4(bh[np][0], bh[np][1], bh[np][2], bh[np][3],
                        sBh + swz(brow[np], kc));
#pragma unroll
            for (int np = 0; np < 2; np++)
                ldsm_x4(bl[np][0], bl[np][1], bl[np][2], bl[np][3],
                        sBl + swz(brow[np], kc));

            // A*Bh + A*Bl (fp32 acc)
#pragma unroll
            for (int mt = 0; mt < 4; mt++)
#pragma unroll
                for (int nt = 0; nt < 4; nt++) {
                    mma16816f(acc[mt][nt], ah[mt], bh[nt >> 1][nt & 1],
                              bh[nt >> 1][(nt & 1) + 2]);
                    mma16816f(acc[mt][nt], ah[mt], bl[nt >> 1][nt & 1],
                              bl[nt >> 1][(nt & 1) + 2]);
                }
        }
    }

    const int rbase = bm * 128 + wm * 64 + (lane >> 2);
    const int cbase = bn * 128 + wn * 32 + (lane & 3) * 2;
#pragma unroll
    for (int mt = 0; mt < 4; mt++)
#pragma unroll
        for (int nt = 0; nt < 4; nt++) {
            int r0 = rbase + mt * 16;
            int col = cbase + nt * 8;
            *reinterpret_cast<float2*>(C + (size_t)r0 * DSZ + col) =
                make_float2(acc[mt][nt][0], acc[mt][nt][1]);
            *reinterpret_cast<float2*>(C + (size_t)(r0 + 8) * DSZ + col) =
                make_float2(acc[mt][nt][2], acc[mt][nt][3]);
        }
}

// ---------------------------------------------------------------------------
// Elementwise / prep kernels
// ---------------------------------------------------------------------------
// hi/lo split of fp32 weights
__global__ void __launch_bounds__(256) wsplit_kernel(const float* __restrict__ in,
                                                     __half* __restrict__ hi,
                                                     __half* __restrict__ lo) {
    size_t i = ((size_t)blockIdx.x * blockDim.x + threadIdx.x) * 4;
    float4 v = *reinterpret_cast<const float4*>(in + i);
    __half h0, h1, h2, h3, l0, l1, l2, l3;
    split_h(v.x, h0, l0); split_h(v.y, h1, l1);
    split_h(v.z, h2, l2); split_h(v.w, h3, l3);
    *reinterpret_cast<uint2*>(hi + i) = make_uint2(pack2h(h0, h1), pack2h(h2, h3));
    *reinterpret_cast<uint2*>(lo + i) = make_uint2(pack2h(l0, l1), pack2h(l2, l3));
}

// Combine wavelet weights: [Wa|Wd] -> [(Wa+Wd)/sqrt2 | (Wa-Wd)/sqrt2], fp16 split
__global__ void __launch_bounds__(256) wavprep_kernel(const float* __restrict__ wavW,
                                                      __half* __restrict__ hi,
                                                      __half* __restrict__ lo) {
    size_t idx = (size_t)blockIdx.x * blockDim.x + threadIdx.x;  // LSZ*DSZ*(DSZ/4)
    int k4 = (int)(idx % (DSZ / 4));
    size_t row = idx / (DSZ / 4);
    const float* base = wavW + row * (2 * DSZ);
    float4 wa = *reinterpret_cast<const float4*>(base + k4 * 4);
    float4 wd = *reinterpret_cast<const float4*>(base + DSZ + k4 * 4);
    float e0 = (wa.x + wd.x) * INV_SQRT2f, e1 = (wa.y + wd.y) * INV_SQRT2f;
    float e2 = (wa.z + wd.z) * INV_SQRT2f, e3 = (wa.w + wd.w) * INV_SQRT2f;
    float o0 = (wa.x - wd.x) * INV_SQRT2f, o1 = (wa.y - wd.y) * INV_SQRT2f;
    float o2 = (wa.z - wd.z) * INV_SQRT2f, o3 = (wa.w - wd.w) * INV_SQRT2f;
    size_t re = row * (2 * DSZ) + k4 * 4;
    size_t ro = re + DSZ;
    __half h0, h1, h2, h3, l0, l1, l2, l3;
    split_h(e0, h0, l0); split_h(e1, h1, l1); split_h(e2, h2, l2); split_h(e3, h3, l3);
    *reinterpret_cast<uint2*>(hi + re) = make_uint2(pack2h(h0, h1), pack2h(h2, h3));
    *reinterpret_cast<uint2*>(lo + re) = make_uint2(pack2h(l0, l1), pack2h(l2, l3));
    split_h(o0, h0, l0); split_h(o1, h1, l1); split_h(o2, h2, l2); split_h(o3, h3, l3);
    *reinterpret_cast<uint2*>(hi + ro) = make_uint2(pack2h(h0, h1), pack2h(h2, h3));
    *reinterpret_cast<uint2*>(lo + ro) = make_uint2(pack2h(l0, l1), pack2h(l2, l3));
}

// Layer-0 input prep: Hx = fp16(x), U = fp16(silu(x))
__global__ void __launch_bounds__(256) xprep_kernel(const float* __restrict__ in,
                                                    __half* __restrict__ Hx,
                                                    __half* __restrict__ U) {
    size_t i = ((size_t)blockIdx.x * blockDim.x + threadIdx.x) * 4;
    float4 v = *reinterpret_cast<const float4*>(in + i);
    *reinterpret_cast<uint2*>(Hx + i) =
        make_uint2(pack2h(__float2half_rn(v.x), __float2half_rn(v.y)),
                   pack2h(__float2half_rn(v.z), __float2half_rn(v.w)));
    *reinterpret_cast<uint2*>(U + i) =
        make_uint2(pack2h(__float2half_rn(silu_f(v.x)), __float2half_rn(silu_f(v.y))),
                   pack2h(__float2half_rn(silu_f(v.z)), __float2half_rn(silu_f(v.w))));
}

__device__ __forceinline__ float block_sum_256(float v) {
    __shared__ float red[8];
    __shared__ float tot;
    int t = threadIdx.x;
#pragma unroll
    for (int o = 16; o > 0; o >>= 1) v += __shfl_xor_sync(0xffffffffu, v, o);
    __syncthreads();
    if ((t & 31) == 0) red[t >> 5] = v;
    __syncthreads();
    if (t == 0) {
        float s = 0.0f;
#pragma unroll
        for (int i = 0; i < 8; i++) s += red[i];
        tot = s;
    }
    __syncthreads();
    return tot;
}

// h = silu(LN(C1[r] + C2[r>>1])); non-final: Hx=fp16(h), U=fp16(silu(h));
// final: fp32 H only.
__global__ void __launch_bounds__(256) lnact_kernel(const float* __restrict__ C1,
                                                    const float* __restrict__ C2,
                                                    const float* __restrict__ gamma,
                                                    const float* __restrict__ beta,
                                                    float* __restrict__ Hout,
                                                    __half* __restrict__ Hx,
                                                    __half* __restrict__ U,
                                                    int final_layer) {
    int r = blockIdx.x;
    int t = threadIdx.x;
    float4 v1 = *reinterpret_cast<const float4*>(C1 + (size_t)r * DSZ + t * 4);
    float4 v2 = *reinterpret_cast<const float4*>(C2 + (size_t)(r >> 1) * DSZ + t * 4);
    float x0 = v1.x + v2.x, x1 = v1.y + v2.y, x2 = v1.z + v2.z, x3 = v1.w + v2.w;

    float mu = block_sum_256(x0 + x1 + x2 + x3) * (1.0f / DSZ);
    float d0 = x0 - mu, d1 = x1 - mu, d2 = x2 - mu, d3 = x3 - mu;
    float var = block_sum_256(d0 * d0 + d1 * d1 + d2 * d2 + d3 * d3) * (1.0f / DSZ);
    float rs = rsqrtf(var + LN_EPSf);

    float4 g4 = *reinterpret_cast<const float4*>(gamma + t * 4);
    float4 b4 = *reinterpret_cast<const float4*>(beta + t * 4);
    float h0 = silu_f(d0 * rs * g4.x + b4.x);
    float h1 = silu_f(d1 * rs * g4.y + b4.y);
    float h2 = silu_f(d2 * rs * g4.z + b4.z);
    float h3 = silu_f(d3 * rs * g4.w + b4.w);

    size_t off = (size_t)r * DSZ + t * 4;
    if (final_layer) {
        *reinterpret_cast<float4*>(Hout + off) = make_float4(h0, h1, h2, h3);
        return;
    }

    *reinterpret_cast<uint2*>(Hx + off) =
        make_uint2(pack2h(__float2half_rn(h0), __float2half_rn(h1)),
                   pack2h(__float2half_rn(h2), __float2half_rn(h3)));
    *reinterpret_cast<uint2*>(U + off) =
        make_uint2(pack2h(__float2half_rn(silu_f(h0)), __float2half_rn(silu_f(h1))),
                   pack2h(__float2half_rn(silu_f(h2)), __float2half_rn(silu_f(h3))));
}

__global__ void __launch_bounds__(1024) pool_kernel(const float* __restrict__ H,
                                                    const float* __restrict__ W,
                                                    const float* __restrict__ ob,
                                                    float* __restrict__ out) {
    __shared__ float red[32];
    int b = blockIdx.x, t = threadIdx.x;
    const float* Hb = H + (size_t)b * SSZ * DSZ + t;
    float cs = 0.0f;
#pragma unroll 8
    for (int s = 0; s < SSZ; s++) cs += Hb[(size_t)s * DSZ];
    float acc = cs * W[t];
#pragma unroll
    for (int o = 16; o > 0; o >>= 1) acc += __shfl_xor_sync(0xffffffffu, acc, o);
    if ((t & 31) == 0) red[t >> 5] = acc;
    __syncthreads();
    if (t < 32) {
        float v = red[t];
#pragma unroll
        for (int o = 16; o > 0; o >>= 1) v += __shfl_xor_sync(0xffffffffu, v, o);
        if (t == 0) out[b] = v * (1.0f / SSZ) + ob[0];
    }
}

// ---------------------------------------------------------------------------
// Launch
// ---------------------------------------------------------------------------
extern "C" void kernel_launch(void* const* d_in, const int* in_sizes, int n_in,
                              void* d_out, int out_size) {
    const float* x     = (const float*)d_in[0];
    const float* baseW = (const float*)d_in[1];
    const float* wavW  = (const float*)d_in[2];
    const float* lng   = (const float*)d_in[3];
    const float* lnb   = (const float*)d_in[4];
    const float* outW  = (const float*)d_in[5];
    const float* outb  = (const float*)d_in[6];
    float* out = (float*)d_out;

    float *H, *C1, *C2;
    __half *U, *Hx, *bWh, *bWl, *wWh, *wWl;
    cudaGetSymbolAddress((void**)&H, g_H);
    cudaGetSymbolAddress((void**)&C1, g_C1);
    cudaGetSymbolAddress((void**)&C2, g_C2);
    cudaGetSymbolAddress((void**)&U, g_U);
    cudaGetSymbolAddress((void**)&Hx, g_Hx);
    cudaGetSymbolAddress((void**)&bWh, g_bWh);
    cudaGetSymbolAddress((void**)&bWl, g_bWl);
    cudaGetSymbolAddress((void**)&wWh, g_wWh);
    cudaGetSymbolAddress((void**)&wWl, g_wWl);

    cudaFuncSetAttribute(gemm_mma, cudaFuncAttributeMaxDynamicSharedMemorySize,
                         GEMM_SMEM);

    // Prep (3 launches; 4th launch below = wav GEMM, ncu's profiled target)
    wsplit_kernel<<<(LSZ * DSZ * DSZ) / 1024, 256>>>(baseW, bWh, bWl);
    wavprep_kernel<<<(LSZ * DSZ * (DSZ / 4)) / 256, 256>>>(wavW, wWh, wWl);
    xprep_kernel<<<(NTOK * DSZ) / 1024, 256>>>(x, Hx, U);

    for (int l = 0; l < LSZ; l++) {
        // wav: H viewed as [8192, 2048] @ combined wW^T
        gemm_mma<<<dim3(DSZ / 128, NPAIR / 128), 256, GEMM_SMEM>>>(
            Hx, wWh + (size_t)l * DSZ * 2 * DSZ, wWl + (size_t)l * DSZ * 2 * DSZ,
            C2, 2 * DSZ);
        // base: U[16384,1024] @ bW^T
        gemm_mma<<<dim3(DSZ / 128, NTOK / 128), 256, GEMM_SMEM>>>(
            U, bWh + (size_t)l * DSZ * DSZ, bWl + (size_t)l * DSZ * DSZ, C1, DSZ);
        lnact_kernel<<<NTOK, 256>>>(C1, C2, lng + l * DSZ, lnb + l * DSZ,
                                    H, Hx, U, (l == LSZ - 1) ? 1 : 0);
    }
    pool_kernel<<<BSZ, 1024>>>(H, outW, outb, out);
}

// round 13
// speedup vs baseline: 2.5022x; 1.5742x over previous
#include <cuda_runtime.h>
#include <cuda_fp16.h>
#include <math.h>
#include <stdint.h>

// Problem constants
#define BSZ 32
#define SSZ 512
#define DSZ 1024
#define LSZ 3
#define NTOK (BSZ * SSZ)   // 16384
#define NPAIR (NTOK / 2)   // 8192
#define INV_SQRT2f 0.70710678118654752440f
#define LN_EPSf 1e-5f

// ---------------------------------------------------------------------------
// Scratch (device globals)
// ---------------------------------------------------------------------------
__device__ float g_H[(size_t)NTOK * DSZ];        // hidden fp32 (final layer)
__device__ float g_C1[(size_t)NTOK * DSZ];
__device__ float g_C2[(size_t)NPAIR * DSZ];
__device__ __half g_U[(size_t)NTOK * DSZ];       // silu(h), fp16 (base GEMM A)
__device__ __half g_Hx[(size_t)NTOK * DSZ];      // h, fp16 (wav GEMM A)
__device__ __half g_bW[(size_t)LSZ * DSZ * DSZ];        // base weights fp16
__device__ __half g_wW[(size_t)LSZ * DSZ * 2 * DSZ];    // combined [We|Wo] fp16

__device__ __forceinline__ float silu_f(float x) {
    return x / (1.0f + __expf(-x));
}

__device__ __forceinline__ uint32_t pack2h(__half a, __half b) {
    __half2 v = __halves2half2(a, b);
    return *reinterpret_cast<uint32_t*>(&v);
}

// ---------------------------------------------------------------------------
// PTX helpers
// ---------------------------------------------------------------------------
__device__ __forceinline__ uint32_t smem_u32(const void* p) {
    uint32_t a;
    asm("{ .reg .u64 t; cvta.to.shared.u64 t, %1; cvt.u32.u64 %0, t; }" : "=r"(a) : "l"(p));
    return a;
}
#define CP_ASYNC16(smem, gmem) \
    asm volatile("cp.async.cg.shared.global [%0], [%1], 16;" \
                 :: "r"((uint32_t)(smem)), "l"(gmem) : "memory")
#define CP_COMMIT() asm volatile("cp.async.commit_group;" ::: "memory")
#define CP_WAIT(n) asm volatile("cp.async.wait_group %0;" :: "n"(n) : "memory")

__device__ __forceinline__ void ldsm_x4(uint32_t& r0, uint32_t& r1, uint32_t& r2,
                                        uint32_t& r3, uint32_t addr) {
    asm volatile("ldmatrix.sync.aligned.m8n8.x4.shared.b16 {%0,%1,%2,%3}, [%4];"
                 : "=r"(r0), "=r"(r1), "=r"(r2), "=r"(r3) : "r"(addr));
}

// fp16 x fp16 -> fp32 accumulate
__device__ __forceinline__ void mma16816f(float* c, const uint32_t* a, uint32_t b0,
                                          uint32_t b1) {
    asm volatile(
        "mma.sync.aligned.m16n8k16.row.col.f32.f16.f16.f32 "
        "{%0,%1,%2,%3}, {%4,%5,%6,%7}, {%8,%9}, {%0,%1,%2,%3};"
        : "+f"(c[0]), "+f"(c[1]), "+f"(c[2]), "+f"(c[3])
        : "r"(a[0]), "r"(a[1]), "r"(a[2]), "r"(a[3]), "r"(b0), "r"(b1));
}

// ---------------------------------------------------------------------------
// GEMM: C[M,1024] = A[M,K] @ B[1024,K]^T, both single fp16 (operand rounding
// 2^-12 rel each; total pipeline error ~4.5e-4, under the 1e-3 gate).
// CTA 128x128, 8 warps of 64x32, BK=32, 3-stage cp.async, 2 CTAs/SM.
// ---------------------------------------------------------------------------
#define BK 32
#define ROWB 64
#define MAT_BYTES (128 * ROWB)        // 8 KB per operand tile
#define STAGE_BYTES (2 * MAT_BYTES)   // A, B = 16 KB
#define NSTAGE 3
#define GEMM_SMEM (NSTAGE * STAGE_BYTES)  // 48 KB

__device__ __forceinline__ uint32_t swz(int row, int chunk) {
    return (uint32_t)(row * ROWB + ((chunk ^ ((row >> 1) & 3)) << 4));
}

__device__ __forceinline__ void load_stage(uint32_t st, const __half* A,
                                           const __half* B, int K, int slab,
                                           int tid) {
    const __half* srcs[2] = {A, B};
#pragma unroll
    for (int m = 0; m < 2; m++) {
        uint32_t mbase = st + m * MAT_BYTES;
        const __half* src = srcs[m];
#pragma unroll
        for (int j = 0; j < 2; j++) {
            int chunk = tid + j * 256;
            int row = chunk >> 2;
            int c = chunk & 3;
            const void* g = src + (size_t)row * K + slab * BK + c * 8;
            CP_ASYNC16(mbase + swz(row, c), g);
        }
    }
}

__global__ void __launch_bounds__(256, 2) gemm_mma(const __half* __restrict__ A,
                                                   const __half* __restrict__ B,
                                                   float* __restrict__ C, int K) {
    extern __shared__ char smem[];
    const uint32_t sb = smem_u32(smem);
    const int tid = threadIdx.x;
    const int wid = tid >> 5;
    const int lane = tid & 31;
    const int wm = wid >> 2;            // 0..1  -> m offset wm*64
    const int wn = wid & 3;             // 0..3  -> n offset wn*32
    const int bm = blockIdx.y, bn = blockIdx.x;

    const __half* At = A + (size_t)bm * 128 * K;
    const __half* Bt = B + (size_t)bn * 128 * K;

    int arow[4], brow[2];
#pragma unroll
    for (int mt = 0; mt < 4; mt++) arow[mt] = wm * 64 + mt * 16 + (lane & 15);
#pragma unroll
    for (int np = 0; np < 2; np++) brow[np] = wn * 32 + np * 16 + (lane & 15);
    const int lchunk = lane >> 4;

    float acc[4][4][4];
#pragma unroll
    for (int i = 0; i < 4; i++)
#pragma unroll
        for (int j = 0; j < 4; j++)
#pragma unroll
            for (int q = 0; q < 4; q++) acc[i][j][q] = 0.0f;

    const int nslab = K / BK;
    load_stage(sb, At, Bt, K, 0, tid);
    CP_COMMIT();
    load_stage(sb + STAGE_BYTES, At, Bt, K, 1, tid);
    CP_COMMIT();

    for (int i = 0; i < nslab; i++) {
        CP_WAIT(1);
        __syncthreads();                // all warps finished stage i-1 compute
        if (i + 2 < nslab) {
            load_stage(sb + ((i + 2) % NSTAGE) * STAGE_BYTES, At, Bt, K, i + 2,
                       tid);
            CP_COMMIT();
        }

        const uint32_t st = sb + (i % NSTAGE) * STAGE_BYTES;
        const uint32_t sA = st;
        const uint32_t sB = st + MAT_BYTES;

#pragma unroll
        for (int ks = 0; ks < BK / 16; ks++) {
            const int kc = lchunk + ks * 2;
            uint32_t ah[4][4], bb[2][4];
#pragma unroll
            for (int mt = 0; mt < 4; mt++)
                ldsm_x4(ah[mt][0], ah[mt][1], ah[mt][2], ah[mt][3],
                        sA + swz(arow[mt], kc));
#pragma unroll
            for (int np = 0; np < 2; np++)
                ldsm_x4(bb[np][0], bb[np][1], bb[np][2], bb[np][3],
                        sB + swz(brow[np], kc));

#pragma unroll
            for (int mt = 0; mt < 4; mt++)
#pragma unroll
                for (int nt = 0; nt < 4; nt++)
                    mma16816f(acc[mt][nt], ah[mt], bb[nt >> 1][nt & 1],
                              bb[nt >> 1][(nt & 1) + 2]);
        }
    }

    const int rbase = bm * 128 + wm * 64 + (lane >> 2);
    const int cbase = bn * 128 + wn * 32 + (lane & 3) * 2;
#pragma unroll
    for (int mt = 0; mt < 4; mt++)
#pragma unroll
        for (int nt = 0; nt < 4; nt++) {
            int r0 = rbase + mt * 16;
            int col = cbase + nt * 8;
            *reinterpret_cast<float2*>(C + (size_t)r0 * DSZ + col) =
                make_float2(acc[mt][nt][0], acc[mt][nt][1]);
            *reinterpret_cast<float2*>(C + (size_t)(r0 + 8) * DSZ + col) =
                make_float2(acc[mt][nt][2], acc[mt][nt][3]);
        }
}

// ---------------------------------------------------------------------------
// Elementwise / prep kernels
// ---------------------------------------------------------------------------
// plain fp32 -> fp16 convert (base weights)
__global__ void __launch_bounds__(256) wconv_kernel(const float* __restrict__ in,
                                                    __half* __restrict__ outw) {
    size_t i = ((size_t)blockIdx.x * blockDim.x + threadIdx.x) * 4;
    float4 v = *reinterpret_cast<const float4*>(in + i);
    *reinterpret_cast<uint2*>(outw + i) =
        make_uint2(pack2h(__float2half_rn(v.x), __float2half_rn(v.y)),
                   pack2h(__float2half_rn(v.z), __float2half_rn(v.w)));
}

// Combine wavelet weights: [Wa|Wd] -> [(Wa+Wd)/sqrt2 | (Wa-Wd)/sqrt2], fp16
__global__ void __launch_bounds__(256) wavprep_kernel(const float* __restrict__ wavW,
                                                      __half* __restrict__ outw) {
    size_t idx = (size_t)blockIdx.x * blockDim.x + threadIdx.x;  // LSZ*DSZ*(DSZ/4)
    int k4 = (int)(idx % (DSZ / 4));
    size_t row = idx / (DSZ / 4);
    const float* base = wavW + row * (2 * DSZ);
    float4 wa = *reinterpret_cast<const float4*>(base + k4 * 4);
    float4 wd = *reinterpret_cast<const float4*>(base + DSZ + k4 * 4);
    float e0 = (wa.x + wd.x) * INV_SQRT2f, e1 = (wa.y + wd.y) * INV_SQRT2f;
    float e2 = (wa.z + wd.z) * INV_SQRT2f, e3 = (wa.w + wd.w) * INV_SQRT2f;
    float o0 = (wa.x - wd.x) * INV_SQRT2f, o1 = (wa.y - wd.y) * INV_SQRT2f;
    float o2 = (wa.z - wd.z) * INV_SQRT2f, o3 = (wa.w - wd.w) * INV_SQRT2f;
    size_t re = row * (2 * DSZ) + k4 * 4;
    size_t ro = re + DSZ;
    *reinterpret_cast<uint2*>(outw + re) =
        make_uint2(pack2h(__float2half_rn(e0), __float2half_rn(e1)),
                   pack2h(__float2half_rn(e2), __float2half_rn(e3)));
    *reinterpret_cast<uint2*>(outw + ro) =
        make_uint2(pack2h(__float2half_rn(o0), __float2half_rn(o1)),
                   pack2h(__float2half_rn(o2), __float2half_rn(o3)));
}

// Layer-0 input prep: Hx = fp16(x), U = fp16(silu(x))
__global__ void __launch_bounds__(256) xprep_kernel(const float* __restrict__ in,
                                                    __half* __restrict__ Hx,
                                                    __half* __restrict__ U) {
    size_t i = ((size_t)blockIdx.x * blockDim.x + threadIdx.x) * 4;
    float4 v = *reinterpret_cast<const float4*>(in + i);
    *reinterpret_cast<uint2*>(Hx + i) =
        make_uint2(pack2h(__float2half_rn(v.x), __float2half_rn(v.y)),
                   pack2h(__float2half_rn(v.z), __float2half_rn(v.w)));
    *reinterpret_cast<uint2*>(U + i) =
        make_uint2(pack2h(__float2half_rn(silu_f(v.x)), __float2half_rn(silu_f(v.y))),
                   pack2h(__float2half_rn(silu_f(v.z)), __float2half_rn(silu_f(v.w))));
}

__device__ __forceinline__ float block_sum_256(float v) {
    __shared__ float red[8];
    __shared__ float tot;
    int t = threadIdx.x;
#pragma unroll
    for (int o = 16; o > 0; o >>= 1) v += __shfl_xor_sync(0xffffffffu, v, o);
    __syncthreads();
    if ((t & 31) == 0) red[t >> 5] = v;
    __syncthreads();
    if (t == 0) {
        float s = 0.0f;
#pragma unroll
        for (int i = 0; i < 8; i++) s += red[i];
        tot = s;
    }
    __syncthreads();
    return tot;
}

// h = silu(LN(C1[r] + C2[r>>1])); non-final: Hx=fp16(h), U=fp16(silu(h));
// final: fp32 H only.
__global__ void __launch_bounds__(256) lnact_kernel(const float* __restrict__ C1,
                                                    const float* __restrict__ C2,
                                                    const float* __restrict__ gamma,
                                                    const float* __restrict__ beta,
                                                    float* __restrict__ Hout,
                                                    __half* __restrict__ Hx,
                                                    __half* __restrict__ U,
                                                    int final_layer) {
    int r = blockIdx.x;
    int t = threadIdx.x;
    float4 v1 = *reinterpret_cast<const float4*>(C1 + (size_t)r * DSZ + t * 4);
    float4 v2 = *reinterpret_cast<const float4*>(C2 + (size_t)(r >> 1) * DSZ + t * 4);
    float x0 = v1.x + v2.x, x1 = v1.y + v2.y, x2 = v1.z + v2.z, x3 = v1.w + v2.w;

    float mu = block_sum_256(x0 + x1 + x2 + x3) * (1.0f / DSZ);
    float d0 = x0 - mu, d1 = x1 - mu, d2 = x2 - mu, d3 = x3 - mu;
    float var = block_sum_256(d0 * d0 + d1 * d1 + d2 * d2 + d3 * d3) * (1.0f / DSZ);
    float rs = rsqrtf(var + LN_EPSf);

    float4 g4 = *reinterpret_cast<const float4*>(gamma + t * 4);
    float4 b4 = *reinterpret_cast<const float4*>(beta + t * 4);
    float h0 = silu_f(d0 * rs * g4.x + b4.x);
    float h1 = silu_f(d1 * rs * g4.y + b4.y);
    float h2 = silu_f(d2 * rs * g4.z + b4.z);
    float h3 = silu_f(d3 * rs * g4.w + b4.w);

    size_t off = (size_t)r * DSZ + t * 4;
    if (final_layer) {
        *reinterpret_cast<float4*>(Hout + off) = make_float4(h0, h1, h2, h3);
        return;
    }

    *reinterpret_cast<uint2*>(Hx + off) =
        make_uint2(pack2h(__float2half_rn(h0), __float2half_rn(h1)),
                   pack2h(__float2half_rn(h2), __float2half_rn(h3)));
    *reinterpret_cast<uint2*>(U + off) =
        make_uint2(pack2h(__float2half_rn(silu_f(h0)), __float2half_rn(silu_f(h1))),
                   pack2h(__float2half_rn(silu_f(h2)), __float2half_rn(silu_f(h3))));
}

__global__ void __launch_bounds__(1024) pool_kernel(const float* __restrict__ H,
                                                    const float* __restrict__ W,
                                                    const float* __restrict__ ob,
                                                    float* __restrict__ out) {
    __shared__ float red[32];
    int b = blockIdx.x, t = threadIdx.x;
    const float* Hb = H + (size_t)b * SSZ * DSZ + t;
    float cs = 0.0f;
#pragma unroll 8
    for (int s = 0; s < SSZ; s++) cs += Hb[(size_t)s * DSZ];
    float acc = cs * W[t];
#pragma unroll
    for (int o = 16; o > 0; o >>= 1) acc += __shfl_xor_sync(0xffffffffu, acc, o);
    if ((t & 31) == 0) red[t >> 5] = acc;
    __syncthreads();
    if (t < 32) {
        float v = red[t];
#pragma unroll
        for (int o = 16; o > 0; o >>= 1) v += __shfl_xor_sync(0xffffffffu, v, o);
        if (t == 0) out[b] = v * (1.0f / SSZ) + ob[0];
    }
}

// ---------------------------------------------------------------------------
// Launch
// ---------------------------------------------------------------------------
extern "C" void kernel_launch(void* const* d_in, const int* in_sizes, int n_in,
                              void* d_out, int out_size) {
    const float* x     = (const float*)d_in[0];
    const float* baseW = (const float*)d_in[1];
    const float* wavW  = (const float*)d_in[2];
    const float* lng   = (const float*)d_in[3];
    const float* lnb   = (const float*)d_in[4];
    const float* outW  = (const float*)d_in[5];
    const float* outb  = (const float*)d_in[6];
    float* out = (float*)d_out;

    float *H, *C1, *C2;
    __half *U, *Hx, *bW, *wW;
    cudaGetSymbolAddress((void**)&H, g_H);
    cudaGetSymbolAddress((void**)&C1, g_C1);
    cudaGetSymbolAddress((void**)&C2, g_C2);
    cudaGetSymbolAddress((void**)&U, g_U);
    cudaGetSymbolAddress((void**)&Hx, g_Hx);
    cudaGetSymbolAddress((void**)&bW, g_bW);
    cudaGetSymbolAddress((void**)&wW, g_wW);

    cudaFuncSetAttribute(gemm_mma, cudaFuncAttributeMaxDynamicSharedMemorySize,
                         GEMM_SMEM);

    // Prep (3 launches; 4th launch below = wav GEMM, ncu's profiled target)
    wconv_kernel<<<(LSZ * DSZ * DSZ) / 1024, 256>>>(baseW, bW);
    wavprep_kernel<<<(LSZ * DSZ * (DSZ / 4)) / 256, 256>>>(wavW, wW);
    xprep_kernel<<<(NTOK * DSZ) / 1024, 256>>>(x, Hx, U);

    for (int l = 0; l < LSZ; l++) {
        // wav: H viewed as [8192, 2048] @ combined wW^T
        gemm_mma<<<dim3(DSZ / 128, NPAIR / 128), 256, GEMM_SMEM>>>(
            Hx, wW + (size_t)l * DSZ * 2 * DSZ, C2, 2 * DSZ);
        // base: U[16384,1024] @ bW^T
        gemm_mma<<<dim3(DSZ / 128, NTOK / 128), 256, GEMM_SMEM>>>(
            U, bW + (size_t)l * DSZ * DSZ, C1, DSZ);
        lnact_kernel<<<NTOK, 256>>>(C1, C2, lng + l * DSZ, lnb + l * DSZ,
                                    H, Hx, U, (l == LSZ - 1) ? 1 : 0);
    }
    pool_kernel<<<BSZ, 1024>>>(H, outW, outb, out);
}

// round 15
// speedup vs baseline: 2.8939x; 1.1566x over previous
#include <cuda_runtime.h>
#include <cuda_fp16.h>
#include <math.h>
#include <stdint.h>

// Problem constants
#define BSZ 32
#define SSZ 512
#define DSZ 1024
#define LSZ 3
#define NTOK (BSZ * SSZ)   // 16384
#define NPAIR (NTOK / 2)   // 8192
#define INV_SQRT2f 0.70710678118654752440f
#define LN_EPSf 1e-5f

#define WAV_CTAS (NPAIR / 128 * (DSZ / 128))   // 512
#define BASE_CTAS (NTOK / 128 * (DSZ / 128))   // 1024

// ---------------------------------------------------------------------------
// Scratch (device globals)
// ---------------------------------------------------------------------------
__device__ __half g_C1[(size_t)NTOK * DSZ];      // base GEMM out (fp16)
__device__ __half g_C2[(size_t)NPAIR * DSZ];     // wav GEMM out (fp16)
__device__ __half g_U[(size_t)NTOK * DSZ];       // silu(h), fp16 (base GEMM A)
__device__ __half g_Hx[(size_t)NTOK * DSZ];      // h, fp16 (wav GEMM A)
__device__ __half g_bW[(size_t)LSZ * DSZ * DSZ];        // base weights fp16
__device__ __half g_wW[(size_t)LSZ * DSZ * 2 * DSZ];    // combined [We|Wo] fp16
__device__ float g_rowdot[NTOK];                  // final-layer per-row dot

__device__ __forceinline__ float silu_f(float x) {
    return x / (1.0f + __expf(-x));
}

__device__ __forceinline__ uint32_t pack2h(__half a, __half b) {
    __half2 v = __halves2half2(a, b);
    return *reinterpret_cast<uint32_t*>(&v);
}

// ---------------------------------------------------------------------------
// PTX helpers
// ---------------------------------------------------------------------------
__device__ __forceinline__ uint32_t smem_u32(const void* p) {
    uint32_t a;
    asm("{ .reg .u64 t; cvta.to.shared.u64 t, %1; cvt.u32.u64 %0, t; }" : "=r"(a) : "l"(p));
    return a;
}
#define CP_ASYNC16(smem, gmem) \
    asm volatile("cp.async.cg.shared.global [%0], [%1], 16;" \
                 :: "r"((uint32_t)(smem)), "l"(gmem) : "memory")
#define CP_COMMIT() asm volatile("cp.async.commit_group;" ::: "memory")
#define CP_WAIT(n) asm volatile("cp.async.wait_group %0;" :: "n"(n) : "memory")

__device__ __forceinline__ void ldsm_x4(uint32_t& r0, uint32_t& r1, uint32_t& r2,
                                        uint32_t& r3, uint32_t addr) {
    asm volatile("ldmatrix.sync.aligned.m8n8.x4.shared.b16 {%0,%1,%2,%3}, [%4];"
                 : "=r"(r0), "=r"(r1), "=r"(r2), "=r"(r3) : "r"(addr));
}

// fp16 x fp16 -> fp32 accumulate
__device__ __forceinline__ void mma16816f(float* c, const uint32_t* a, uint32_t b0,
                                          uint32_t b1) {
    asm volatile(
        "mma.sync.aligned.m16n8k16.row.col.f32.f16.f16.f32 "
        "{%0,%1,%2,%3}, {%4,%5,%6,%7}, {%8,%9}, {%0,%1,%2,%3};"
        : "+f"(c[0]), "+f"(c[1]), "+f"(c[2]), "+f"(c[3])
        : "r"(a[0]), "r"(a[1]), "r"(a[2]), "r"(a[3]), "r"(b0), "r"(b1));
}

// ---------------------------------------------------------------------------
// Dual GEMM, one launch: CTAs [0,512) do wav (Hx[8192,2048] @ wW^T -> C2),
// CTAs [512,1536) do base (U[16384,1024] @ bW^T -> C1). fp16 in, fp16 out,
// fp32 TC accumulate. CTA 128x128, 8 warps of 64x32, BK=32, 3-stage cp.async.
// ---------------------------------------------------------------------------
#define BK 32
#define ROWB 64
#define MAT_BYTES (128 * ROWB)        // 8 KB per operand tile
#define STAGE_BYTES (2 * MAT_BYTES)   // A, B = 16 KB
#define NSTAGE 3
#define GEMM_SMEM (NSTAGE * STAGE_BYTES)  // 48 KB

__device__ __forceinline__ uint32_t swz(int row, int chunk) {
    return (uint32_t)(row * ROWB + ((chunk ^ ((row >> 1) & 3)) << 4));
}

__device__ __forceinline__ void load_stage(uint32_t st, const __half* A,
                                           const __half* B, int K, int slab,
                                           int tid) {
    const __half* srcs[2] = {A, B};
#pragma unroll
    for (int m = 0; m < 2; m++) {
        uint32_t mbase = st + m * MAT_BYTES;
        const __half* src = srcs[m];
#pragma unroll
        for (int j = 0; j < 2; j++) {
            int chunk = tid + j * 256;
            int row = chunk >> 2;
            int c = chunk & 3;
            const void* g = src + (size_t)row * K + slab * BK + c * 8;
            CP_ASYNC16(mbase + swz(row, c), g);
        }
    }
}

__global__ void __launch_bounds__(256, 2) gemm_dual(const __half* __restrict__ Aw,
                                                    const __half* __restrict__ Bw,
                                                    __half* __restrict__ Cw,
                                                    const __half* __restrict__ Ab,
                                                    const __half* __restrict__ Bb,
                                                    __half* __restrict__ Cb) {
    extern __shared__ char smem[];
    const uint32_t sb = smem_u32(smem);
    const int tid = threadIdx.x;
    const int wid = tid >> 5;
    const int lane = tid & 31;
    const int wm = wid >> 2;            // 0..1  -> m offset wm*64
    const int wn = wid & 3;             // 0..3  -> n offset wn*32

    // CTA role select
    const __half* A;
    const __half* B;
    __half* C;
    int K, bm, bn;
    if (blockIdx.x < WAV_CTAS) {
        int c = blockIdx.x;
        A = Aw; B = Bw; C = Cw; K = 2 * DSZ;
        bn = c & 7; bm = c >> 3;
    } else {
        int c = blockIdx.x - WAV_CTAS;
        A = Ab; B = Bb; C = Cb; K = DSZ;
        bn = c & 7; bm = c >> 3;
    }

    const __half* At = A + (size_t)bm * 128 * K;
    const __half* Bt = B + (size_t)bn * 128 * K;

    int arow[4], brow[2];
#pragma unroll
    for (int mt = 0; mt < 4; mt++) arow[mt] = wm * 64 + mt * 16 + (lane & 15);
#pragma unroll
    for (int np = 0; np < 2; np++) brow[np] = wn * 32 + np * 16 + (lane & 15);
    const int lchunk = lane >> 4;

    float acc[4][4][4];
#pragma unroll
    for (int i = 0; i < 4; i++)
#pragma unroll
        for (int j = 0; j < 4; j++)
#pragma unroll
            for (int q = 0; q < 4; q++) acc[i][j][q] = 0.0f;

    const int nslab = K / BK;
    load_stage(sb, At, Bt, K, 0, tid);
    CP_COMMIT();
    load_stage(sb + STAGE_BYTES, At, Bt, K, 1, tid);
    CP_COMMIT();

    for (int i = 0; i < nslab; i++) {
        CP_WAIT(1);
        __syncthreads();                // all warps finished stage i-1 compute
        if (i + 2 < nslab) {
            load_stage(sb + ((i + 2) % NSTAGE) * STAGE_BYTES, At, Bt, K, i + 2,
                       tid);
            CP_COMMIT();
        }

        const uint32_t st = sb + (i % NSTAGE) * STAGE_BYTES;
        const uint32_t sA = st;
        const uint32_t sB = st + MAT_BYTES;

#pragma unroll
        for (int ks = 0; ks < BK / 16; ks++) {
            const int kc = lchunk + ks * 2;
            uint32_t ah[4][4], bb[2][4];
#pragma unroll
            for (int mt = 0; mt < 4; mt++)
                ldsm_x4(ah[mt][0], ah[mt][1], ah[mt][2], ah[mt][3],
                        sA + swz(arow[mt], kc));
#pragma unroll
            for (int np = 0; np < 2; np++)
                ldsm_x4(bb[np][0], bb[np][1], bb[np][2], bb[np][3],
                        sB + swz(brow[np], kc));

#pragma unroll
            for (int mt = 0; mt < 4; mt++)
#pragma unroll
                for (int nt = 0; nt < 4; nt++)
                    mma16816f(acc[mt][nt], ah[mt], bb[nt >> 1][nt & 1],
                              bb[nt >> 1][(nt & 1) + 2]);
        }
    }

    // Epilogue: fp16 store (half2 per fragment row)
    const int rbase = bm * 128 + wm * 64 + (lane >> 2);
    const int cbase = bn * 128 + wn * 32 + (lane & 3) * 2;
#pragma unroll
    for (int mt = 0; mt < 4; mt++)
#pragma unroll
        for (int nt = 0; nt < 4; nt++) {
            int r0 = rbase + mt * 16;
            int col = cbase + nt * 8;
            *reinterpret_cast<uint32_t*>(C + (size_t)r0 * DSZ + col) =
                pack2h(__float2half_rn(acc[mt][nt][0]),
                       __float2half_rn(acc[mt][nt][1]));
            *reinterpret_cast<uint32_t*>(C + (size_t)(r0 + 8) * DSZ + col) =
                pack2h(__float2half_rn(acc[mt][nt][2]),
                       __float2half_rn(acc[mt][nt][3]));
        }
}

// ---------------------------------------------------------------------------
// Elementwise / prep kernels
// ---------------------------------------------------------------------------
// plain fp32 -> fp16 convert (base weights)
__global__ void __launch_bounds__(256) wconv_kernel(const float* __restrict__ in,
                                                    __half* __restrict__ outw) {
    size_t i = ((size_t)blockIdx.x * blockDim.x + threadIdx.x) * 4;
    float4 v = *reinterpret_cast<const float4*>(in + i);
    *reinterpret_cast<uint2*>(outw + i) =
        make_uint2(pack2h(__float2half_rn(v.x), __float2half_rn(v.y)),
                   pack2h(__float2half_rn(v.z), __float2half_rn(v.w)));
}

// Combine wavelet weights: [Wa|Wd] -> [(Wa+Wd)/sqrt2 | (Wa-Wd)/sqrt2], fp16
__global__ void __launch_bounds__(256) wavprep_kernel(const float* __restrict__ wavW,
                                                      __half* __restrict__ outw) {
    size_t idx = (size_t)blockIdx.x * blockDim.x + threadIdx.x;  // LSZ*DSZ*(DSZ/4)
    int k4 = (int)(idx % (DSZ / 4));
    size_t row = idx / (DSZ / 4);
    const float* base = wavW + row * (2 * DSZ);
    float4 wa = *reinterpret_cast<const float4*>(base + k4 * 4);
    float4 wd = *reinterpret_cast<const float4*>(base + DSZ + k4 * 4);
    float e0 = (wa.x + wd.x) * INV_SQRT2f, e1 = (wa.y + wd.y) * INV_SQRT2f;
    float e2 = (wa.z + wd.z) * INV_SQRT2f, e3 = (wa.w + wd.w) * INV_SQRT2f;
    float o0 = (wa.x - wd.x) * INV_SQRT2f, o1 = (wa.y - wd.y) * INV_SQRT2f;
    float o2 = (wa.z - wd.z) * INV_SQRT2f, o3 = (wa.w - wd.w) * INV_SQRT2f;
    size_t re = row * (2 * DSZ) + k4 * 4;
    size_t ro = re + DSZ;
    *reinterpret_cast<uint2*>(outw + re) =
        make_uint2(pack2h(__float2half_rn(e0), __float2half_rn(e1)),
                   pack2h(__float2half_rn(e2), __float2half_rn(e3)));
    *reinterpret_cast<uint2*>(outw + ro) =
        make_uint2(pack2h(__float2half_rn(o0), __float2half_rn(o1)),
                   pack2h(__float2half_rn(o2), __float2half_rn(o3)));
}

// Layer-0 input prep: Hx = fp16(x), U = fp16(silu(x))
__global__ void __launch_bounds__(256) xprep_kernel(const float* __restrict__ in,
                                                    __half* __restrict__ Hx,
                                                    __half* __restrict__ U) {
    size_t i = ((size_t)blockIdx.x * blockDim.x + threadIdx.x) * 4;
    float4 v = *reinterpret_cast<const float4*>(in + i);
    *reinterpret_cast<uint2*>(Hx + i) =
        make_uint2(pack2h(__float2half_rn(v.x), __float2half_rn(v.y)),
                   pack2h(__float2half_rn(v.z), __float2half_rn(v.w)));
    *reinterpret_cast<uint2*>(U + i) =
        make_uint2(pack2h(__float2half_rn(silu_f(v.x)), __float2half_rn(silu_f(v.y))),
                   pack2h(__float2half_rn(silu_f(v.z)), __float2half_rn(silu_f(v.w))));
}

__device__ __forceinline__ float block_sum_256(float v) {
    __shared__ float red[8];
    __shared__ float tot;
    int t = threadIdx.x;
#pragma unroll
    for (int o = 16; o > 0; o >>= 1) v += __shfl_xor_sync(0xffffffffu, v, o);
    __syncthreads();
    if ((t & 31) == 0) red[t >> 5] = v;
    __syncthreads();
    if (t == 0) {
        float s = 0.0f;
#pragma unroll
        for (int i = 0; i < 8; i++) s += red[i];
        tot = s;
    }
    __syncthreads();
    return tot;
}

// h = silu(LN(C1[r] + C2[r>>1])), fp16 GEMM outputs.
// non-final: Hx=fp16(h), U=fp16(silu(h)).
// final: rowdot[r] = h . outW  (deterministic block reduction).
__global__ void __launch_bounds__(256) lnact_kernel(const __half* __restrict__ C1,
                                                    const __half* __restrict__ C2,
                                                    const float* __restrict__ gamma,
                                                    const float* __restrict__ beta,
                                                    __half* __restrict__ Hx,
                                                    __half* __restrict__ U,
                                                    const float* __restrict__ outW,
                                                    float* __restrict__ rowdot,
                                                    int final_layer) {
    int r = blockIdx.x;
    int t = threadIdx.x;
    uint2 u1 = *reinterpret_cast<const uint2*>(C1 + (size_t)r * DSZ + t * 4);
    uint2 u2 = *reinterpret_cast<const uint2*>(C2 + (size_t)(r >> 1) * DSZ + t * 4);
    float2 a01 = __half22float2(*reinterpret_cast<__half2*>(&u1.x));
    float2 a23 = __half22float2(*reinterpret_cast<__half2*>(&u1.y));
    float2 b01 = __half22float2(*reinterpret_cast<__half2*>(&u2.x));
    float2 b23 = __half22float2(*reinterpret_cast<__half2*>(&u2.y));
    float x0 = a01.x + b01.x, x1 = a01.y + b01.y;
    float x2 = a23.x + b23.x, x3 = a23.y + b23.y;

    float mu = block_sum_256(x0 + x1 + x2 + x3) * (1.0f / DSZ);
    float d0 = x0 - mu, d1 = x1 - mu, d2 = x2 - mu, d3 = x3 - mu;
    float var = block_sum_256(d0 * d0 + d1 * d1 + d2 * d2 + d3 * d3) * (1.0f / DSZ);
    float rs = rsqrtf(var + LN_EPSf);

    float4 g4 = *reinterpret_cast<const float4*>(gamma + t * 4);
    float4 b4 = *reinterpret_cast<const float4*>(beta + t * 4);
    float h0 = silu_f(d0 * rs * g4.x + b4.x);
    float h1 = silu_f(d1 * rs * g4.y + b4.y);
    float h2 = silu_f(d2 * rs * g4.z + b4.z);
    float h3 = silu_f(d3 * rs * g4.w + b4.w);

    if (final_layer) {
        float4 w4 = *reinterpret_cast<const float4*>(outW + t * 4);
        float dot = block_sum_256(h0 * w4.x + h1 * w4.y + h2 * w4.z + h3 * w4.w);
        if (t == 0) rowdot[r] = dot;
        return;
    }

    size_t off = (size_t)r * DSZ + t * 4;
    *reinterpret_cast<uint2*>(Hx + off) =
        make_uint2(pack2h(__float2half_rn(h0), __float2half_rn(h1)),
                   pack2h(__float2half_rn(h2), __float2half_rn(h3)));
    *reinterpret_cast<uint2*>(U + off) =
        make_uint2(pack2h(__float2half_rn(silu_f(h0)), __float2half_rn(silu_f(h1))),
                   pack2h(__float2half_rn(silu_f(h2)), __float2half_rn(silu_f(h3))));
}

// out[b] = mean_s rowdot[b*SSZ + s] + out_b   (deterministic)
__global__ void __launch_bounds__(256) pool2_kernel(const float* __restrict__ rowdot,
                                                    const float* __restrict__ ob,
                                                    float* __restrict__ out) {
    int b = blockIdx.x, t = threadIdx.x;
    float v = rowdot[b * SSZ + t] + rowdot[b * SSZ + 256 + t];
    float s = block_sum_256(v);
    if (t == 0) out[b] = s * (1.0f / SSZ) + ob[0];
}

// ---------------------------------------------------------------------------
// Launch
// ---------------------------------------------------------------------------
extern "C" void kernel_launch(void* const* d_in, const int* in_sizes, int n_in,
                              void* d_out, int out_size) {
    const float* x     = (const float*)d_in[0];
    const float* baseW = (const float*)d_in[1];
    const float* wavW  = (const float*)d_in[2];
    const float* lng   = (const float*)d_in[3];
    const float* lnb   = (const float*)d_in[4];
    const float* outW  = (const float*)d_in[5];
    const float* outb  = (const float*)d_in[6];
    float* out = (float*)d_out;

    __half *C1, *C2, *U, *Hx, *bW, *wW;
    float* rowdot;
    cudaGetSymbolAddress((void**)&C1, g_C1);
    cudaGetSymbolAddress((void**)&C2, g_C2);
    cudaGetSymbolAddress((void**)&U, g_U);
    cudaGetSymbolAddress((void**)&Hx, g_Hx);
    cudaGetSymbolAddress((void**)&bW, g_bW);
    cudaGetSymbolAddress((void**)&wW, g_wW);
    cudaGetSymbolAddress((void**)&rowdot, g_rowdot);

    cudaFuncSetAttribute(gemm_dual, cudaFuncAttributeMaxDynamicSharedMemorySize,
                         GEMM_SMEM);

    // Prep (3 launches; 4th launch = merged dual GEMM, ncu's profiled target)
    wconv_kernel<<<(LSZ * DSZ * DSZ) / 1024, 256>>>(baseW, bW);
    wavprep_kernel<<<(LSZ * DSZ * (DSZ / 4)) / 256, 256>>>(wavW, wW);
    xprep_kernel<<<(NTOK * DSZ) / 1024, 256>>>(x, Hx, U);

    for (int l = 0; l < LSZ; l++) {
        gemm_dual<<<WAV_CTAS + BASE_CTAS, 256, GEMM_SMEM>>>(
            Hx, wW + (size_t)l * DSZ * 2 * DSZ, C2,
            U, bW + (size_t)l * DSZ * DSZ, C1);
        lnact_kernel<<<NTOK, 256>>>(C1, C2, lng + l * DSZ, lnb + l * DSZ,
                                    Hx, U, outW, rowdot,
                                    (l == LSZ - 1) ? 1 : 0);
    }
    pool2_kernel<<<BSZ, 256>>>(rowdot, outb, out);
}

// round 17
// speedup vs baseline: 3.1393x; 1.0848x over previous
#include <cuda_runtime.h>
#include <cuda_fp16.h>
#include <math.h>
#include <stdint.h>

// Problem constants
#define BSZ 32
#define SSZ 512
#define DSZ 1024
#define LSZ 3
#define NTOK (BSZ * SSZ)   // 16384
#define NPAIR (NTOK / 2)   // 8192
#define INV_SQRT2f 0.70710678118654752440f
#define LN_EPSf 1e-5f

#define WAV_CTAS (NPAIR / 128 * (DSZ / 128))   // 512
#define BASE_CTAS (NTOK / 128 * (DSZ / 128))   // 1024

// ---------------------------------------------------------------------------
// Scratch (device globals)
// ---------------------------------------------------------------------------
__device__ __half g_C1[(size_t)NTOK * DSZ];      // base GEMM out (fp16)
__device__ __half g_C2[(size_t)NPAIR * DSZ];     // wav GEMM out (fp16)
__device__ __half g_U[(size_t)NTOK * DSZ];       // silu(h), fp16 (base GEMM A)
__device__ __half g_Hx[(size_t)NTOK * DSZ];      // h, fp16 (wav GEMM A)
__device__ __half g_bW[(size_t)LSZ * DSZ * DSZ];        // base weights fp16
__device__ __half g_wW[(size_t)LSZ * DSZ * 2 * DSZ];    // combined [We|Wo] fp16
__device__ float g_rowdot[NTOK];                  // final-layer per-row dot

__device__ __forceinline__ float silu_f(float x) {
    return x / (1.0f + __expf(-x));
}

__device__ __forceinline__ uint32_t pack2h(__half a, __half b) {
    __half2 v = __halves2half2(a, b);
    return *reinterpret_cast<uint32_t*>(&v);
}

// ---------------------------------------------------------------------------
// PTX helpers
// ---------------------------------------------------------------------------
__device__ __forceinline__ uint32_t smem_u32(const void* p) {
    uint32_t a;
    asm("{ .reg .u64 t; cvta.to.shared.u64 t, %1; cvt.u32.u64 %0, t; }" : "=r"(a) : "l"(p));
    return a;
}
#define CP_ASYNC16(smem, gmem) \
    asm volatile("cp.async.cg.shared.global [%0], [%1], 16;" \
                 :: "r"((uint32_t)(smem)), "l"(gmem) : "memory")
#define CP_COMMIT() asm volatile("cp.async.commit_group;" ::: "memory")
#define CP_WAIT(n) asm volatile("cp.async.wait_group %0;" :: "n"(n) : "memory")

__device__ __forceinline__ void ldsm_x4(uint32_t& r0, uint32_t& r1, uint32_t& r2,
                                        uint32_t& r3, uint32_t addr) {
    asm volatile("ldmatrix.sync.aligned.m8n8.x4.shared.b16 {%0,%1,%2,%3}, [%4];"
                 : "=r"(r0), "=r"(r1), "=r"(r2), "=r"(r3) : "r"(addr));
}

// fp16 x fp16 -> fp32 accumulate
__device__ __forceinline__ void mma16816f(float* c, const uint32_t* a, uint32_t b0,
                                          uint32_t b1) {
    asm volatile(
        "mma.sync.aligned.m16n8k16.row.col.f32.f16.f16.f32 "
        "{%0,%1,%2,%3}, {%4,%5,%6,%7}, {%8,%9}, {%0,%1,%2,%3};"
        : "+f"(c[0]), "+f"(c[1]), "+f"(c[2]), "+f"(c[3])
        : "r"(a[0]), "r"(a[1]), "r"(a[2]), "r"(a[3]), "r"(b0), "r"(b1));
}

// ---------------------------------------------------------------------------
// Dual GEMM, one launch: CTAs [0,512) do wav (Hx[8192,2048] @ wW^T -> C2),
// CTAs [512,1536) do base (U[16384,1024] @ bW^T -> C1). fp16 in/out, fp32 TC
// accumulate. CTA 128x128, 8 warps of 64x32, BK=64 (128B rows, SW128 swizzle
// chunk^=row&7), 3-stage cp.async, 2 CTAs/SM. Addressing strength-reduced.
// ---------------------------------------------------------------------------
#define BK 64
#define ROWB 128
#define MAT_BYTES (128 * ROWB)        // 16 KB per operand tile
#define STAGE_BYTES (2 * MAT_BYTES)   // A, B = 32 KB
#define NSTAGE 3
#define GEMM_SMEM (NSTAGE * STAGE_BYTES)  // 96 KB

__global__ void __launch_bounds__(256, 2) gemm_dual(const __half* __restrict__ Aw,
                                                    const __half* __restrict__ Bw,
                                                    __half* __restrict__ Cw,
                                                    const __half* __restrict__ Ab,
                                                    const __half* __restrict__ Bb,
                                                    __half* __restrict__ Cb) {
    extern __shared__ char smem[];
    const uint32_t sb = smem_u32(smem);
    const int tid = threadIdx.x;
    const int wid = tid >> 5;
    const int lane = tid & 31;
    const int wm = wid >> 2;            // 0..1  -> m offset wm*64
    const int wn = wid & 3;             // 0..3  -> n offset wn*32

    // CTA role select
    const __half* A;
    const __half* B;
    __half* C;
    int K, bm, bn;
    if (blockIdx.x < WAV_CTAS) {
        int c = blockIdx.x;
        A = Aw; B = Bw; C = Cw; K = 2 * DSZ;
        bn = c & 7; bm = c >> 3;
    } else {
        int c = blockIdx.x - WAV_CTAS;
        A = Ab; B = Bb; C = Cb; K = DSZ;
        bn = c & 7; bm = c >> 3;
    }

    // --- Strength-reduced cp.async addressing ---
    // chunk = tid + q*256 (q=0..3): row = tid>>3 + q*32, col-chunk c = tid&7
    // swizzle XOR term ((c ^ (row&7))<<4) is invariant in q (32 ≡ 0 mod 8).
    const int lrow = tid >> 3;          // 0..31
    const int lcol = tid & 7;
    const uint32_t s0 = (uint32_t)(lrow * ROWB) + (uint32_t)(((lcol ^ (lrow & 7)) << 4));
    const __half* pA = A + (size_t)(bm * 128 + lrow) * K + lcol * 8;
    const __half* pB = B + (size_t)(bn * 128 + lrow) * K + lcol * 8;
    const size_t row32 = (size_t)32 * K;   // gmem stride of one q-group

    // --- LDSM addressing ---
    int arB[4], brB[2];
#pragma unroll
    for (int mt = 0; mt < 4; mt++)
        arB[mt] = (wm * 64 + mt * 16 + (lane & 15)) * ROWB;
#pragma unroll
    for (int np = 0; np < 2; np++)
        brB[np] = (wn * 32 + np * 16 + (lane & 15)) * ROWB + MAT_BYTES;
    const int l7 = lane & 7;
    const int lchunk = lane >> 4;

    float acc[4][4][4];
#pragma unroll
    for (int i = 0; i < 4; i++)
#pragma unroll
        for (int j = 0; j < 4; j++)
#pragma unroll
            for (int q = 0; q < 4; q++) acc[i][j][q] = 0.0f;

    const int nslab = K / BK;

    // Prologue: slabs 0, 1 into stages 0, 1
#pragma unroll
    for (int s = 0; s < 2; s++) {
        const __half* a0 = pA + s * BK;
        const __half* b0 = pB + s * BK;
        uint32_t stg = sb + s * STAGE_BYTES;
#pragma unroll
        for (int q = 0; q < 4; q++) {
            CP_ASYNC16(stg + s0 + q * (32 * ROWB), a0 + (size_t)q * row32);
            CP_ASYNC16(stg + MAT_BYTES + s0 + q * (32 * ROWB), b0 + (size_t)q * row32);
        }
        CP_COMMIT();
    }

    uint32_t st_cmp = sb;
    uint32_t st_load = sb + 2 * STAGE_BYTES;

    for (int i = 0; i < nslab; i++) {
        CP_WAIT(1);
        __syncthreads();                // all warps finished stage reuse target
        if (i + 2 < nslab) {
            const __half* a0 = pA + (i + 2) * BK;
            const __half* b0 = pB + (i + 2) * BK;
#pragma unroll
            for (int q = 0; q < 4; q++) {
                CP_ASYNC16(st_load + s0 + q * (32 * ROWB), a0 + (size_t)q * row32);
                CP_ASYNC16(st_load + MAT_BYTES + s0 + q * (32 * ROWB),
                           b0 + (size_t)q * row32);
            }
        }
        CP_COMMIT();                    // empty group on tail keeps wait invariant

#pragma unroll
        for (int ks = 0; ks < BK / 16; ks++) {
            const int xo = ((lchunk + ks * 2) ^ l7) << 4;
            uint32_t ah[4][4], bb[2][4];
#pragma unroll
            for (int mt = 0; mt < 4; mt++)
                ldsm_x4(ah[mt][0], ah[mt][1], ah[mt][2], ah[mt][3],
                        st_cmp + arB[mt] + xo);
#pragma unroll
            for (int np = 0; np < 2; np++)
                ldsm_x4(bb[np][0], bb[np][1], bb[np][2], bb[np][3],
                        st_cmp + brB[np] + xo);

#pragma unroll
            for (int mt = 0; mt < 4; mt++)
#pragma unroll
                for (int nt = 0; nt < 4; nt++)
                    mma16816f(acc[mt][nt], ah[mt], bb[nt >> 1][nt & 1],
                              bb[nt >> 1][(nt & 1) + 2]);
        }

        st_cmp += STAGE_BYTES;
        if (st_cmp == sb + GEMM_SMEM) st_cmp = sb;
        st_load += STAGE_BYTES;
        if (st_load == sb + GEMM_SMEM) st_load = sb;
    }

    // Epilogue: fp16 store (half2 per fragment row)
    const int rbase = bm * 128 + wm * 64 + (lane >> 2);
    const int cbase = bn * 128 + wn * 32 + (lane & 3) * 2;
#pragma unroll
    for (int mt = 0; mt < 4; mt++)
#pragma unroll
        for (int nt = 0; nt < 4; nt++) {
            int r0 = rbase + mt * 16;
            int col = cbase + nt * 8;
            *reinterpret_cast<uint32_t*>(C + (size_t)r0 * DSZ + col) =
                pack2h(__float2half_rn(acc[mt][nt][0]),
                       __float2half_rn(acc[mt][nt][1]));
            *reinterpret_cast<uint32_t*>(C + (size_t)(r0 + 8) * DSZ + col) =
                pack2h(__float2half_rn(acc[mt][nt][2]),
                       __float2half_rn(acc[mt][nt][3]));
        }
}

// ---------------------------------------------------------------------------
// Elementwise / prep kernels
// ---------------------------------------------------------------------------
// plain fp32 -> fp16 convert (base weights)
__global__ void __launch_bounds__(256) wconv_kernel(const float* __restrict__ in,
                                                    __half* __restrict__ outw) {
    size_t i = ((size_t)blockIdx.x * blockDim.x + threadIdx.x) * 4;
    float4 v = *reinterpret_cast<const float4*>(in + i);
    *reinterpret_cast<uint2*>(outw + i) =
        make_uint2(pack2h(__float2half_rn(v.x), __float2half_rn(v.y)),
                   pack2h(__float2half_rn(v.z), __float2half_rn(v.w)));
}

// Combine wavelet weights: [Wa|Wd] -> [(Wa+Wd)/sqrt2 | (Wa-Wd)/sqrt2], fp16
__global__ void __launch_bounds__(256) wavprep_kernel(const float* __restrict__ wavW,
                                                      __half* __restrict__ outw) {
    size_t idx = (size_t)blockIdx.x * blockDim.x + threadIdx.x;  // LSZ*DSZ*(DSZ/4)
    int k4 = (int)(idx % (DSZ / 4));
    size_t row = idx / (DSZ / 4);
    const float* base = wavW + row * (2 * DSZ);
    float4 wa = *reinterpret_cast<const float4*>(base + k4 * 4);
    float4 wd = *reinterpret_cast<const float4*>(base + DSZ + k4 * 4);
    float e0 = (wa.x + wd.x) * INV_SQRT2f, e1 = (wa.y + wd.y) * INV_SQRT2f;
    float e2 = (wa.z + wd.z) * INV_SQRT2f, e3 = (wa.w + wd.w) * INV_SQRT2f;
    float o0 = (wa.x - wd.x) * INV_SQRT2f, o1 = (wa.y - wd.y) * INV_SQRT2f;
    float o2 = (wa.z - wd.z) * INV_SQRT2f, o3 = (wa.w - wd.w) * INV_SQRT2f;
    size_t re = row * (2 * DSZ) + k4 * 4;
    size_t ro = re + DSZ;
    *reinterpret_cast<uint2*>(outw + re) =
        make_uint2(pack2h(__float2half_rn(e0), __float2half_rn(e1)),
                   pack2h(__float2half_rn(e2), __float2half_rn(e3)));
    *reinterpret_cast<uint2*>(outw + ro) =
        make_uint2(pack2h(__float2half_rn(o0), __float2half_rn(o1)),
                   pack2h(__float2half_rn(o2), __float2half_rn(o3)));
}

// Layer-0 input prep: Hx = fp16(x), U = fp16(silu(x))
__global__ void __launch_bounds__(256) xprep_kernel(const float* __restrict__ in,
                                                    __half* __restrict__ Hx,
                                                    __half* __restrict__ U) {
    size_t i = ((size_t)blockIdx.x * blockDim.x + threadIdx.x) * 4;
    float4 v = *reinterpret_cast<const float4*>(in + i);
    *reinterpret_cast<uint2*>(Hx + i) =
        make_uint2(pack2h(__float2half_rn(v.x), __float2half_rn(v.y)),
                   pack2h(__float2half_rn(v.z), __float2half_rn(v.w)));
    *reinterpret_cast<uint2*>(U + i) =
        make_uint2(pack2h(__float2half_rn(silu_f(v.x)), __float2half_rn(silu_f(v.y))),
                   pack2h(__float2half_rn(silu_f(v.z)), __float2half_rn(silu_f(v.w))));
}

__device__ __forceinline__ float block_sum_256(float v) {
    __shared__ float red[8];
    __shared__ float tot;
    int t = threadIdx.x;
#pragma unroll
    for (int o = 16; o > 0; o >>= 1) v += __shfl_xor_sync(0xffffffffu, v, o);
    __syncthreads();
    if ((t & 31) == 0) red[t >> 5] = v;
    __syncthreads();
    if (t == 0) {
        float s = 0.0f;
#pragma unroll
        for (int i = 0; i < 8; i++) s += red[i];
        tot = s;
    }
    __syncthreads();
    return tot;
}

// h = silu(LN(C1[r] + C2[r>>1])), fp16 GEMM outputs.
// non-final: Hx=fp16(h), U=fp16(silu(h)).
// final: rowdot[r] = h . outW  (deterministic block reduction).
__global__ void __launch_bounds__(256) lnact_kernel(const __half* __restrict__ C1,
                                                    const __half* __restrict__ C2,
                                                    const float* __restrict__ gamma,
                                                    const float* __restrict__ beta,
                                                    __half* __restrict__ Hx,
                                                    __half* __restrict__ U,
                                                    const float* __restrict__ outW,
                                                    float* __restrict__ rowdot,
                                                    int final_layer) {
    int r = blockIdx.x;
    int t = threadIdx.x;
    uint2 u1 = *reinterpret_cast<const uint2*>(C1 + (size_t)r * DSZ + t * 4);
    uint2 u2 = *reinterpret_cast<const uint2*>(C2 + (size_t)(r >> 1) * DSZ + t * 4);
    float2 a01 = __half22float2(*reinterpret_cast<__half2*>(&u1.x));
    float2 a23 = __half22float2(*reinterpret_cast<__half2*>(&u1.y));
    float2 b01 = __half22float2(*reinterpret_cast<__half2*>(&u2.x));
    float2 b23 = __half22float2(*reinterpret_cast<__half2*>(&u2.y));
    float x0 = a01.x + b01.x, x1 = a01.y + b01.y;
    float x2 = a23.x + b23.x, x3 = a23.y + b23.y;

    float mu = block_sum_256(x0 + x1 + x2 + x3) * (1.0f / DSZ);
    float d0 = x0 - mu, d1 = x1 - mu, d2 = x2 - mu, d3 = x3 - mu;
    float var = block_sum_256(d0 * d0 + d1 * d1 + d2 * d2 + d3 * d3) * (1.0f / DSZ);
    float rs = rsqrtf(var + LN_EPSf);

    float4 g4 = *reinterpret_cast<const float4*>(gamma + t * 4);
    float4 b4 = *reinterpret_cast<const float4*>(beta + t * 4);
    float h0 = silu_f(d0 * rs * g4.x + b4.x);
    float h1 = silu_f(d1 * rs * g4.y + b4.y);
    float h2 = silu_f(d2 * rs * g4.z + b4.z);
    float h3 = silu_f(d3 * rs * g4.w + b4.w);

    if (final_layer) {
        float4 w4 = *reinterpret_cast<const float4*>(outW + t * 4);
        float dot = block_sum_256(h0 * w4.x + h1 * w4.y + h2 * w4.z + h3 * w4.w);
        if (t == 0) rowdot[r] = dot;
        return;
    }

    size_t off = (size_t)r * DSZ + t * 4;
    *reinterpret_cast<uint2*>(Hx + off) =
        make_uint2(pack2h(__float2half_rn(h0), __float2half_rn(h1)),
                   pack2h(__float2half_rn(h2), __float2half_rn(h3)));
    *reinterpret_cast<uint2*>(U + off) =
        make_uint2(pack2h(__float2half_rn(silu_f(h0)), __float2half_rn(silu_f(h1))),
                   pack2h(__float2half_rn(silu_f(h2)), __float2half_rn(silu_f(h3))));
}

// out[b] = mean_s rowdot[b*SSZ + s] + out_b   (deterministic)
__global__ void __launch_bounds__(256) pool2_kernel(const float* __restrict__ rowdot,
                                                    const float* __restrict__ ob,
                                                    float* __restrict__ out) {
    int b = blockIdx.x, t = threadIdx.x;
    float v = rowdot[b * SSZ + t] + rowdot[b * SSZ + 256 + t];
    float s = block_sum_256(v);
    if (t == 0) out[b] = s * (1.0f / SSZ) + ob[0];
}

// ---------------------------------------------------------------------------
// Launch
// ---------------------------------------------------------------------------
extern "C" void kernel_launch(void* const* d_in, const int* in_sizes, int n_in,
                              void* d_out, int out_size) {
    const float* x     = (const float*)d_in[0];
    const float* baseW = (const float*)d_in[1];
    const float* wavW  = (const float*)d_in[2];
    const float* lng   = (const float*)d_in[3];
    const float* lnb   = (const float*)d_in[4];
    const float* outW  = (const float*)d_in[5];
    const float* outb  = (const float*)d_in[6];
    float* out = (float*)d_out;

    __half *C1, *C2, *U, *Hx, *bW, *wW;
    float* rowdot;
    cudaGetSymbolAddress((void**)&C1, g_C1);
    cudaGetSymbolAddress((void**)&C2, g_C2);
    cudaGetSymbolAddress((void**)&U, g_U);
    cudaGetSymbolAddress((void**)&Hx, g_Hx);
    cudaGetSymbolAddress((void**)&bW, g_bW);
    cudaGetSymbolAddress((void**)&wW, g_wW);
    cudaGetSymbolAddress((void**)&rowdot, g_rowdot);

    cudaFuncSetAttribute(gemm_dual, cudaFuncAttributeMaxDynamicSharedMemorySize,
                         GEMM_SMEM);

    // Prep (3 launches; 4th launch = merged dual GEMM, ncu's profiled target)
    wconv_kernel<<<(LSZ * DSZ * DSZ) / 1024, 256>>>(baseW, bW);
    wavprep_kernel<<<(LSZ * DSZ * (DSZ / 4)) / 256, 256>>>(wavW, wW);
    xprep_kernel<<<(NTOK * DSZ) / 1024, 256>>>(x, Hx, U);

    for (int l = 0; l < LSZ; l++) {
        gemm_dual<<<WAV_CTAS + BASE_CTAS, 256, GEMM_SMEM>>>(
            Hx, wW + (size_t)l * DSZ * 2 * DSZ, C2,
            U, bW + (size_t)l * DSZ * DSZ, C1);
        lnact_kernel<<<NTOK, 256>>>(C1, C2, lng + l * DSZ, lnb + l * DSZ,
                                    Hx, U, outW, rowdot,
                                    (l == LSZ - 1) ? 1 : 0);
    }
    pool2_kernel<<<BSZ, 256>>>(rowdot, outb, out);
}